// round 1
// baseline (speedup 1.0000x reference)
#include <cuda_runtime.h>

#define NBATCH 2
#define SEQ    1024
#define HID    2048
#define NH     32
#define HD     64

// ---- scratch (device globals: allocation-free) ----
__device__ float g_Q[(size_t)NBATCH * NH * SEQ * HD];   // [b,h,l,d]
__device__ float g_K[(size_t)NBATCH * NH * SEQ * HD];   // [b,h,l,d]
__device__ float g_V[(size_t)NBATCH * NH * SEQ * HD];   // [b,h,l,d]
__device__ float g_O[(size_t)NBATCH * SEQ * HID];       // [b,l,h*d] flat

// ============================================================
// GEMM: C = A @ W^T.  A [2048,2048] row-major, W [2048,2048] row-major
// (rows of W are output features, so both operands are K-major).
// 64x64 tile, BK=32, 256 threads, 4x4 micro-tile, float4 smem reads.
// HEADSPLIT=1 writes C[b,h,l,d] (one head per 64-wide N tile).
// ============================================================
template <int HEADSPLIT>
__device__ __forceinline__ void gemm_body(const float* __restrict__ A,
                                          const float* __restrict__ W,
                                          float* __restrict__ C)
{
    __shared__ float As[32][68];   // [k][m]
    __shared__ float Bs[32][68];   // [k][n]
    const int tid = threadIdx.x;
    const int tx = tid & 15, ty = tid >> 4;
    const int m0 = blockIdx.y * 64, n0 = blockIdx.x * 64;
    const int rr = tid >> 3;            // 0..31
    const int cc = (tid & 7) << 2;      // 0..28 step 4
    float acc[4][4] = {};

    for (int k0 = 0; k0 < HID; k0 += 32) {
#pragma unroll
        for (int p = 0; p < 2; p++) {
            const int r = p * 32 + rr;
            float4 av = *(const float4*)(A + (size_t)(m0 + r) * HID + k0 + cc);
            As[cc + 0][r] = av.x; As[cc + 1][r] = av.y;
            As[cc + 2][r] = av.z; As[cc + 3][r] = av.w;
            float4 wv = *(const float4*)(W + (size_t)(n0 + r) * HID + k0 + cc);
            Bs[cc + 0][r] = wv.x; Bs[cc + 1][r] = wv.y;
            Bs[cc + 2][r] = wv.z; Bs[cc + 3][r] = wv.w;
        }
        __syncthreads();
#pragma unroll
        for (int kk = 0; kk < 32; kk++) {
            const float4 a4 = *(const float4*)&As[kk][ty * 4];
            const float4 b4 = *(const float4*)&Bs[kk][tx * 4];
            const float ar[4] = {a4.x, a4.y, a4.z, a4.w};
            const float br[4] = {b4.x, b4.y, b4.z, b4.w};
#pragma unroll
            for (int ii = 0; ii < 4; ii++)
#pragma unroll
                for (int jj = 0; jj < 4; jj++)
                    acc[ii][jj] += ar[ii] * br[jj];
        }
        __syncthreads();
    }

#pragma unroll
    for (int ii = 0; ii < 4; ii++) {
        const int m = m0 + ty * 4 + ii;
        float4 v = make_float4(acc[ii][0], acc[ii][1], acc[ii][2], acc[ii][3]);
        if (HEADSPLIT) {
            const int b = m >> 10;          // m / SEQ
            const int l = m & (SEQ - 1);
            const int h = blockIdx.x;       // one head per N tile (HD == 64)
            *(float4*)(C + (((size_t)b * NH + h) * SEQ + l) * HD + tx * 4) = v;
        } else {
            *(float4*)(C + (size_t)m * HID + n0 + tx * 4) = v;
        }
    }
}

__global__ void __launch_bounds__(256)
qkv_gemm(const float* __restrict__ X, const float* __restrict__ Wq,
         const float* __restrict__ Wk, const float* __restrict__ Wv)
{
    if (blockIdx.z == 0)      gemm_body<1>(X, Wq, g_Q);
    else if (blockIdx.z == 1) gemm_body<1>(X, Wk, g_K);
    else                      gemm_body<1>(X, Wv, g_V);
}

__global__ void __launch_bounds__(256)
out_gemm(const float* __restrict__ Wo, float* __restrict__ Out)
{
    gemm_body<0>(g_O, Wo, Out);
}

// ============================================================
// Stick-breaking attention, product form:
//   att[i,j] = sigmoid(z_ij) * prod_{j<k<i} (1 - sigmoid(z_ik))
// Flash-style: 64 queries per block, key tiles processed from high j
// to low j, per-row suffix product carried in registers (scan threads),
// O accumulated in 4x4 register micro-tiles.
// ============================================================
#define ATTN_SMEM (4 * 64 * 68 * 4)

__global__ void __launch_bounds__(256) sba_attn()
{
    extern __shared__ float sm[];
    float(*Qs)[68] = (float(*)[68])(sm);                 // [d][i]
    float(*Ks)[68] = (float(*)[68])(sm + 64 * 68);       // [d][j]
    float(*Vs)[68] = (float(*)[68])(sm + 2 * 64 * 68);   // [j][d]
    float(*Ss)[68] = (float(*)[68])(sm + 3 * 64 * 68);   // [j][i] sig -> att

    const int tid = threadIdx.x;
    const int tx = tid & 15, ty = tid >> 4;
    const int ti = (gridDim.x - 1) - blockIdx.x;  // heavy (large ti) blocks first
    const int bh = blockIdx.y;
    const size_t base = (size_t)bh * SEQ * HD;
    const float* Qp = g_Q + base;
    const float* Kp = g_K + base;
    const float* Vp = g_V + base;
    const int i0 = ti * 64;

    // load Q tile transposed [d][i]
    {
        const int r = tid >> 4;             // 0..15
        const int c = (tid & 15) * 4;       // 0..60
#pragma unroll
        for (int p = 0; p < 4; p++) {
            const int i = p * 16 + r;
            float4 q = *(const float4*)(Qp + (size_t)(i0 + i) * HD + c);
            Qs[c + 0][i] = q.x; Qs[c + 1][i] = q.y;
            Qs[c + 2][i] = q.z; Qs[c + 3][i] = q.w;
        }
    }

    float oacc[4][4] = {};
    float accp = 1.0f;   // per-row suffix product (used by scan threads tid<64)

    for (int tj = ti; tj >= 0; tj--) {
        const int j0 = tj * 64;
        // load K (transposed) and V tiles
        {
            const int r = tid >> 4;
            const int c = (tid & 15) * 4;
#pragma unroll
            for (int p = 0; p < 4; p++) {
                const int j = p * 16 + r;
                float4 k4 = *(const float4*)(Kp + (size_t)(j0 + j) * HD + c);
                Ks[c + 0][j] = k4.x; Ks[c + 1][j] = k4.y;
                Ks[c + 2][j] = k4.z; Ks[c + 3][j] = k4.w;
                float4 v4 = *(const float4*)(Vp + (size_t)(j0 + j) * HD + c);
                *(float4*)&Vs[j][c] = v4;
            }
        }
        __syncthreads();

        // ---- z = Q K^T / 8, sigmoid + causal mask, store sig into Ss[j][i]
        float z[4][4] = {};
#pragma unroll
        for (int d = 0; d < 64; d++) {
            const float4 a4 = *(const float4*)&Qs[d][ty * 4];
            const float4 b4 = *(const float4*)&Ks[d][tx * 4];
            const float ar[4] = {a4.x, a4.y, a4.z, a4.w};
            const float br[4] = {b4.x, b4.y, b4.z, b4.w};
#pragma unroll
            for (int ii = 0; ii < 4; ii++)
#pragma unroll
                for (int jj = 0; jj < 4; jj++)
                    z[ii][jj] += ar[ii] * br[jj];
        }
        const bool diag = (tj == ti);
#pragma unroll
        for (int jj = 0; jj < 4; jj++) {
            float s[4];
#pragma unroll
            for (int ii = 0; ii < 4; ii++) {
                const float zv = z[ii][jj] * 0.125f;
                float sv = __fdividef(1.0f, 1.0f + __expf(-zv));
                if (diag) {
                    const int gi = 4 * ty + ii, gj = 4 * tx + jj;
                    if (gj >= gi) sv = 0.0f;   // strictly causal: j < i
                }
                s[ii] = sv;
            }
            *(float4*)&Ss[tx * 4 + jj][ty * 4] = make_float4(s[0], s[1], s[2], s[3]);
        }
        __syncthreads();

        // ---- reverse scan within tile: att = sig * suffix_prod; prod *= (1-sig)
        if (tid < 64) {
            float acc = accp;
#pragma unroll
            for (int j = 63; j >= 0; j--) {
                const float sv = Ss[j][tid];
                Ss[j][tid] = sv * acc;
                acc *= (1.0f - sv);
            }
            accp = acc;
        }
        __syncthreads();

        // ---- O += att @ V
#pragma unroll
        for (int j = 0; j < 64; j++) {
            const float4 a4 = *(const float4*)&Ss[j][ty * 4];
            const float4 v4 = *(const float4*)&Vs[j][tx * 4];
            const float ar[4] = {a4.x, a4.y, a4.z, a4.w};
            const float vr[4] = {v4.x, v4.y, v4.z, v4.w};
#pragma unroll
            for (int ii = 0; ii < 4; ii++)
#pragma unroll
                for (int dd = 0; dd < 4; dd++)
                    oacc[ii][dd] += ar[ii] * vr[dd];
        }
        __syncthreads();
    }

    // write O in flat [b, l, h*64+d] layout for the output GEMM
    const int b = bh >> 5, h = bh & 31;
#pragma unroll
    for (int ii = 0; ii < 4; ii++) {
        const int i = i0 + ty * 4 + ii;
        float4 v = make_float4(oacc[ii][0], oacc[ii][1], oacc[ii][2], oacc[ii][3]);
        *(float4*)(g_O + ((size_t)b * SEQ + i) * HID + h * HD + tx * 4) = v;
    }
}

// ============================================================
extern "C" void kernel_launch(void* const* d_in, const int* in_sizes, int n_in,
                              void* d_out, int out_size)
{
    const float* X  = (const float*)d_in[0];
    const float* Wq = (const float*)d_in[1];
    const float* Wk = (const float*)d_in[2];
    const float* Wv = (const float*)d_in[3];
    const float* Wo = (const float*)d_in[4];
    float* Out = (float*)d_out;

    cudaFuncSetAttribute(sba_attn, cudaFuncAttributeMaxDynamicSharedMemorySize,
                         ATTN_SMEM);

    qkv_gemm<<<dim3(HID / 64, (NBATCH * SEQ) / 64, 3), 256>>>(X, Wq, Wk, Wv);
    sba_attn<<<dim3(SEQ / 64, NBATCH * NH), 256, ATTN_SMEM>>>();
    out_gemm<<<dim3(HID / 64, (NBATCH * SEQ) / 64), 256>>>(Wo, Out);
}

// round 3
// speedup vs baseline: 1.8939x; 1.8939x over previous
#include <cuda_runtime.h>
#include <cuda_bf16.h>
#include <cstdint>

#define NBATCH 2
#define SEQ    1024
#define HID    2048
#define NH     32
#define HD     64

// ======================= scratch =======================
__device__ float g_Q[(size_t)NBATCH * NH * SEQ * HD];
__device__ float g_K[(size_t)NBATCH * NH * SEQ * HD];
__device__ float g_V[(size_t)NBATCH * NH * SEQ * HD];
__device__ float g_O[(size_t)NBATCH * SEQ * HID];

__device__ __nv_bfloat16 g_Xhi[(size_t)NBATCH * SEQ * HID];
__device__ __nv_bfloat16 g_Xlo[(size_t)NBATCH * SEQ * HID];
__device__ __nv_bfloat16 g_Whi[4][(size_t)HID * HID];   // q,k,v,o
__device__ __nv_bfloat16 g_Wlo[4][(size_t)HID * HID];
__device__ __nv_bfloat16 g_Ohi[(size_t)NBATCH * SEQ * HID];
__device__ __nv_bfloat16 g_Olo[(size_t)NBATCH * SEQ * HID];

// ======================= helpers =======================
__device__ __forceinline__ uint32_t smem_u32(const void* p) {
    uint32_t a;
    asm("{ .reg .u64 t; cvta.to.shared.u64 t, %1; cvt.u32.u64 %0, t; }"
        : "=r"(a) : "l"(p));
    return a;
}
__device__ __forceinline__ void ldsm_x4(uint32_t* r, uint32_t addr) {
    asm volatile("ldmatrix.sync.aligned.m8n8.x4.shared.b16 {%0,%1,%2,%3}, [%4];"
                 : "=r"(r[0]), "=r"(r[1]), "=r"(r[2]), "=r"(r[3]) : "r"(addr));
}
__device__ __forceinline__ void ldsm_x2(uint32_t* r, uint32_t addr) {
    asm volatile("ldmatrix.sync.aligned.m8n8.x2.shared.b16 {%0,%1}, [%2];"
                 : "=r"(r[0]), "=r"(r[1]) : "r"(addr));
}
__device__ __forceinline__ void mma16816(float* c, const uint32_t* a,
                                         const uint32_t* b) {
    asm volatile(
        "mma.sync.aligned.m16n8k16.row.col.f32.bf16.bf16.f32 "
        "{%0,%1,%2,%3}, {%4,%5,%6,%7}, {%8,%9}, {%0,%1,%2,%3};"
        : "+f"(c[0]), "+f"(c[1]), "+f"(c[2]), "+f"(c[3])
        : "r"(a[0]), "r"(a[1]), "r"(a[2]), "r"(a[3]), "r"(b[0]), "r"(b[1]));
}

// ======================= fp32 -> bf16 hi/lo split =======================
__device__ __forceinline__ void split_store(const float* __restrict__ src,
                                            __nv_bfloat16* __restrict__ hi,
                                            __nv_bfloat16* __restrict__ lo,
                                            size_t i4) {
    float4 v = *(const float4*)(src + i4);
    float f[4] = {v.x, v.y, v.z, v.w};
    ushort4 h, l;
    unsigned short* hp = &h.x;
    unsigned short* lp = &l.x;
#pragma unroll
    for (int k = 0; k < 4; k++) {
        __nv_bfloat16 bh = __float2bfloat16_rn(f[k]);
        __nv_bfloat16 bl = __float2bfloat16_rn(f[k] - __bfloat162float(bh));
        hp[k] = __bfloat16_as_ushort(bh);
        lp[k] = __bfloat16_as_ushort(bl);
    }
    *(ushort4*)(hi + i4) = h;
    *(ushort4*)(lo + i4) = l;
}

__global__ void __launch_bounds__(256)
split5(const float* __restrict__ X, const float* __restrict__ Wq,
       const float* __restrict__ Wk, const float* __restrict__ Wv,
       const float* __restrict__ Wo) {
    const float* src;
    __nv_bfloat16 *hi, *lo;
    switch (blockIdx.z) {
        case 0: src = X;  hi = g_Xhi;    lo = g_Xlo;    break;
        case 1: src = Wq; hi = g_Whi[0]; lo = g_Wlo[0]; break;
        case 2: src = Wk; hi = g_Whi[1]; lo = g_Wlo[1]; break;
        case 3: src = Wv; hi = g_Whi[2]; lo = g_Wlo[2]; break;
        default: src = Wo; hi = g_Whi[3]; lo = g_Wlo[3]; break;
    }
    size_t i4 = ((size_t)blockIdx.x * 256 + threadIdx.x) * 4;
    split_store(src, hi, lo, i4);
}

__global__ void __launch_bounds__(256) splitO() {
    size_t i4 = ((size_t)blockIdx.x * 256 + threadIdx.x) * 4;
    split_store(g_O, g_Ohi, g_Olo, i4);
}

// ======================= HMMA bf16-split GEMM =======================
// C[M,N] = A @ W^T, A [M,2048] row-major, W [N,2048] row-major (K-major both).
// CTA: 128x128 tile, BK=32. 8 warps (2m x 4n), warp tile 64x32 = 4x4 m16n8.
// 3 passes: hi*hi + hi*lo + lo*hi.
#define SMSTRIDE 40   // bf16 elems per row (80B): conflict-free for ldmatrix

template <int HEADSPLIT>
__device__ __forceinline__ void hmma_gemm_body(
    const __nv_bfloat16* __restrict__ Ahi, const __nv_bfloat16* __restrict__ Alo,
    const __nv_bfloat16* __restrict__ Bhi, const __nv_bfloat16* __restrict__ Blo,
    float* __restrict__ C)
{
    __shared__ __align__(16) uint16_t sAhi[128 * SMSTRIDE];
    __shared__ __align__(16) uint16_t sAlo[128 * SMSTRIDE];
    __shared__ __align__(16) uint16_t sBhi[128 * SMSTRIDE];
    __shared__ __align__(16) uint16_t sBlo[128 * SMSTRIDE];

    const int tid = threadIdx.x;
    const int wid = tid >> 5, lane = tid & 31;
    const int warp_m = (wid >> 2) * 64;      // 0 or 64
    const int warp_n = (wid & 3) * 32;       // 0,32,64,96
    const int m0 = blockIdx.y * 128, n0 = blockIdx.x * 128;

    const uint32_t baseAhi = smem_u32(sAhi);
    const uint32_t baseAlo = smem_u32(sAlo);
    const uint32_t baseBhi = smem_u32(sBhi);
    const uint32_t baseBlo = smem_u32(sBlo);

    // gmem->smem mapping: 4 threads per 64B row
    const int lr = tid >> 2;          // 0..63
    const int seg = tid & 3;          // 0..3

    // ldmatrix address offsets (bytes) within a tile
    const uint32_t a_row = (lane & 15);
    const uint32_t a_koff = (lane >> 4) * 8;          // 0 or 8 elems
    const uint32_t b_row = (lane & 7);
    const uint32_t b_koff = ((lane >> 3) & 1) * 8;    // 0 or 8 elems

    float acc[4][4][4] = {};

    for (int k0 = 0; k0 < HID; k0 += 32) {
#pragma unroll
        for (int p = 0; p < 2; p++) {
            const int r = p * 64 + lr;
            const uint32_t so = (uint32_t)(r * SMSTRIDE + seg * 8) * 2;
            const size_t ga = (size_t)(m0 + r) * HID + k0 + seg * 8;
            const size_t gb = (size_t)(n0 + r) * HID + k0 + seg * 8;
            *(uint4*)((char*)sAhi + so) = *(const uint4*)(Ahi + ga);
            *(uint4*)((char*)sAlo + so) = *(const uint4*)(Alo + ga);
            *(uint4*)((char*)sBhi + so) = *(const uint4*)(Bhi + gb);
            *(uint4*)((char*)sBlo + so) = *(const uint4*)(Blo + gb);
        }
        __syncthreads();

#pragma unroll
        for (int kk = 0; kk < 32; kk += 16) {
            uint32_t ahi[4][4], alo[4][4], bhi[4][2], blo[4][2];
#pragma unroll
            for (int mi = 0; mi < 4; mi++) {
                const uint32_t off =
                    (uint32_t)((warp_m + mi * 16 + a_row) * SMSTRIDE +
                               kk + a_koff) * 2;
                ldsm_x4(ahi[mi], baseAhi + off);
                ldsm_x4(alo[mi], baseAlo + off);
            }
#pragma unroll
            for (int ni = 0; ni < 4; ni++) {
                const uint32_t off =
                    (uint32_t)((warp_n + ni * 8 + b_row) * SMSTRIDE +
                               kk + b_koff) * 2;
                ldsm_x2(bhi[ni], baseBhi + off);
                ldsm_x2(blo[ni], baseBlo + off);
            }
#pragma unroll
            for (int mi = 0; mi < 4; mi++)
#pragma unroll
                for (int ni = 0; ni < 4; ni++) {
                    mma16816(acc[mi][ni], ahi[mi], bhi[ni]);
                    mma16816(acc[mi][ni], ahi[mi], blo[ni]);
                    mma16816(acc[mi][ni], alo[mi], bhi[ni]);
                }
        }
        __syncthreads();
    }

    // epilogue
    const int tr = lane >> 2;            // 0..7
    const int tc = (lane & 3) * 2;       // 0,2,4,6
#pragma unroll
    for (int mi = 0; mi < 4; mi++) {
#pragma unroll
        for (int ni = 0; ni < 4; ni++) {
            const int col = n0 + warp_n + ni * 8 + tc;
#pragma unroll
            for (int half = 0; half < 2; half++) {
                const int row = m0 + warp_m + mi * 16 + half * 8 + tr;
                float2 v = make_float2(acc[mi][ni][half * 2],
                                       acc[mi][ni][half * 2 + 1]);
                if (HEADSPLIT) {
                    const int b = row >> 10, l = row & (SEQ - 1);
                    const int h = col >> 6, d = col & 63;
                    *(float2*)(C + (((size_t)b * NH + h) * SEQ + l) * HD + d) = v;
                } else {
                    *(float2*)(C + (size_t)row * HID + col) = v;
                }
            }
        }
    }
}

__global__ void __launch_bounds__(256) qkv_mma() {
    float* outs[3] = {g_Q, g_K, g_V};
    const int z = blockIdx.z;
    hmma_gemm_body<1>(g_Xhi, g_Xlo, g_Whi[z], g_Wlo[z], outs[z]);
}

__global__ void __launch_bounds__(256) out_mma(float* Out) {
    hmma_gemm_body<0>(g_Ohi, g_Olo, g_Whi[3], g_Wlo[3], Out);
}

// ======================= stick-breaking attention =======================
#define ATTN_SMEM (4 * 64 * 68 * 4)

__global__ void __launch_bounds__(256) sba_attn()
{
    extern __shared__ float sm[];
    float(*Qs)[68] = (float(*)[68])(sm);
    float(*Ks)[68] = (float(*)[68])(sm + 64 * 68);
    float(*Vs)[68] = (float(*)[68])(sm + 2 * 64 * 68);
    float(*Ss)[68] = (float(*)[68])(sm + 3 * 64 * 68);

    const int tid = threadIdx.x;
    const int tx = tid & 15, ty = tid >> 4;
    const int ti = (gridDim.x - 1) - blockIdx.x;
    const int bh = blockIdx.y;
    const size_t base = (size_t)bh * SEQ * HD;
    const float* Qp = g_Q + base;
    const float* Kp = g_K + base;
    const float* Vp = g_V + base;
    const int i0 = ti * 64;

    {
        const int r = tid >> 4;
        const int c = (tid & 15) * 4;
#pragma unroll
        for (int p = 0; p < 4; p++) {
            const int i = p * 16 + r;
            float4 q = *(const float4*)(Qp + (size_t)(i0 + i) * HD + c);
            Qs[c + 0][i] = q.x; Qs[c + 1][i] = q.y;
            Qs[c + 2][i] = q.z; Qs[c + 3][i] = q.w;
        }
    }

    float oacc[4][4] = {};
    float accp = 1.0f;

    for (int tj = ti; tj >= 0; tj--) {
        const int j0 = tj * 64;
        {
            const int r = tid >> 4;
            const int c = (tid & 15) * 4;
#pragma unroll
            for (int p = 0; p < 4; p++) {
                const int j = p * 16 + r;
                float4 k4 = *(const float4*)(Kp + (size_t)(j0 + j) * HD + c);
                Ks[c + 0][j] = k4.x; Ks[c + 1][j] = k4.y;
                Ks[c + 2][j] = k4.z; Ks[c + 3][j] = k4.w;
                float4 v4 = *(const float4*)(Vp + (size_t)(j0 + j) * HD + c);
                *(float4*)&Vs[j][c] = v4;
            }
        }
        __syncthreads();

        float z[4][4] = {};
#pragma unroll
        for (int d = 0; d < 64; d++) {
            const float4 a4 = *(const float4*)&Qs[d][ty * 4];
            const float4 b4 = *(const float4*)&Ks[d][tx * 4];
            const float ar[4] = {a4.x, a4.y, a4.z, a4.w};
            const float br[4] = {b4.x, b4.y, b4.z, b4.w};
#pragma unroll
            for (int ii = 0; ii < 4; ii++)
#pragma unroll
                for (int jj = 0; jj < 4; jj++)
                    z[ii][jj] += ar[ii] * br[jj];
        }
        const bool diag = (tj == ti);
#pragma unroll
        for (int jj = 0; jj < 4; jj++) {
            float s[4];
#pragma unroll
            for (int ii = 0; ii < 4; ii++) {
                const float zv = z[ii][jj] * 0.125f;
                float sv = __fdividef(1.0f, 1.0f + __expf(-zv));
                if (diag) {
                    const int gi = 4 * ty + ii, gj = 4 * tx + jj;
                    if (gj >= gi) sv = 0.0f;
                }
                s[ii] = sv;
            }
            *(float4*)&Ss[tx * 4 + jj][ty * 4] = make_float4(s[0], s[1], s[2], s[3]);
        }
        __syncthreads();

        if (tid < 64) {
            float acc = accp;
#pragma unroll
            for (int j = 63; j >= 0; j--) {
                const float sv = Ss[j][tid];
                Ss[j][tid] = sv * acc;
                acc *= (1.0f - sv);
            }
            accp = acc;
        }
        __syncthreads();

#pragma unroll
        for (int j = 0; j < 64; j++) {
            const float4 a4 = *(const float4*)&Ss[j][ty * 4];
            const float4 v4 = *(const float4*)&Vs[j][tx * 4];
            const float ar[4] = {a4.x, a4.y, a4.z, a4.w};
            const float vr[4] = {v4.x, v4.y, v4.z, v4.w};
#pragma unroll
            for (int ii = 0; ii < 4; ii++)
#pragma unroll
                for (int dd = 0; dd < 4; dd++)
                    oacc[ii][dd] += ar[ii] * vr[dd];
        }
        __syncthreads();
    }

    const int b = bh >> 5, h = bh & 31;
#pragma unroll
    for (int ii = 0; ii < 4; ii++) {
        const int i = i0 + ty * 4 + ii;
        float4 v = make_float4(oacc[ii][0], oacc[ii][1], oacc[ii][2], oacc[ii][3]);
        *(float4*)(g_O + ((size_t)b * SEQ + i) * HID + h * HD + tx * 4) = v;
    }
}

// ======================= launch =======================
extern "C" void kernel_launch(void* const* d_in, const int* in_sizes, int n_in,
                              void* d_out, int out_size)
{
    const float* X  = (const float*)d_in[0];
    const float* Wq = (const float*)d_in[1];
    const float* Wk = (const float*)d_in[2];
    const float* Wv = (const float*)d_in[3];
    const float* Wo = (const float*)d_in[4];
    float* Out = (float*)d_out;

    cudaFuncSetAttribute(sba_attn, cudaFuncAttributeMaxDynamicSharedMemorySize,
                         ATTN_SMEM);

    split5<<<dim3((HID * HID / 4) / 256, 1, 5), 256>>>(X, Wq, Wk, Wv, Wo);
    qkv_mma<<<dim3(HID / 128, (NBATCH * SEQ) / 128, 3), 256>>>();
    sba_attn<<<dim3(SEQ / 64, NBATCH * NH), 256, ATTN_SMEM>>>();
    splitO<<<dim3((NBATCH * SEQ * HID / 4) / 256, 1, 1), 256>>>();
    out_mma<<<dim3(HID / 128, (NBATCH * SEQ) / 128, 1), 256>>>(Out);
}

// round 4
// speedup vs baseline: 2.9386x; 1.5516x over previous
#include <cuda_runtime.h>
#include <cuda_bf16.h>
#include <cstdint>

#define NBATCH 2
#define SEQ    1024
#define HID    2048
#define NH     32
#define HD     64

// ======================= scratch =======================
#define QKV_ELEMS ((size_t)NBATCH * NH * SEQ * HD)
__device__ __nv_bfloat16 g_Xhi[(size_t)NBATCH * SEQ * HID];
__device__ __nv_bfloat16 g_Xlo[(size_t)NBATCH * SEQ * HID];
__device__ __nv_bfloat16 g_Whi[4][(size_t)HID * HID];   // q,k,v,o
__device__ __nv_bfloat16 g_Wlo[4][(size_t)HID * HID];
__device__ __nv_bfloat16 g_Qhi[QKV_ELEMS], g_Qlo[QKV_ELEMS];   // [b,h,l,d], pre-scaled 1/8
__device__ __nv_bfloat16 g_Khi[QKV_ELEMS], g_Klo[QKV_ELEMS];   // [b,h,l,d]
__device__ __nv_bfloat16 g_Vthi[QKV_ELEMS], g_Vtlo[QKV_ELEMS]; // [b,h,d,l] transposed
__device__ __nv_bfloat16 g_Ohi[(size_t)NBATCH * SEQ * HID];
__device__ __nv_bfloat16 g_Olo[(size_t)NBATCH * SEQ * HID];

// ======================= helpers =======================
__device__ __forceinline__ uint32_t smem_u32(const void* p) {
    uint32_t a;
    asm("{ .reg .u64 t; cvta.to.shared.u64 t, %1; cvt.u32.u64 %0, t; }"
        : "=r"(a) : "l"(p));
    return a;
}
__device__ __forceinline__ void ldsm_x4(uint32_t* r, uint32_t addr) {
    asm volatile("ldmatrix.sync.aligned.m8n8.x4.shared.b16 {%0,%1,%2,%3}, [%4];"
                 : "=r"(r[0]), "=r"(r[1]), "=r"(r[2]), "=r"(r[3]) : "r"(addr));
}
__device__ __forceinline__ void ldsm_x2(uint32_t* r, uint32_t addr) {
    asm volatile("ldmatrix.sync.aligned.m8n8.x2.shared.b16 {%0,%1}, [%2];"
                 : "=r"(r[0]), "=r"(r[1]) : "r"(addr));
}
__device__ __forceinline__ void mma16816(float* c, const uint32_t* a,
                                         const uint32_t* b) {
    asm volatile(
        "mma.sync.aligned.m16n8k16.row.col.f32.bf16.bf16.f32 "
        "{%0,%1,%2,%3}, {%4,%5,%6,%7}, {%8,%9}, {%0,%1,%2,%3};"
        : "+f"(c[0]), "+f"(c[1]), "+f"(c[2]), "+f"(c[3])
        : "r"(a[0]), "r"(a[1]), "r"(a[2]), "r"(a[3]), "r"(b[0]), "r"(b[1]));
}
#define CP16(dst, src) \
    asm volatile("cp.async.cg.shared.global [%0], [%1], 16;" \
                 :: "r"(dst), "l"(src) : "memory")
#define CP_COMMIT asm volatile("cp.async.commit_group;" ::: "memory")
#define CP_WAIT0  asm volatile("cp.async.wait_group 0;" ::: "memory")

__device__ __forceinline__ void split2(float v, __nv_bfloat16& h, __nv_bfloat16& l) {
    h = __float2bfloat16_rn(v);
    l = __float2bfloat16_rn(v - __bfloat162float(h));
}

// ======================= fp32 -> bf16 hi/lo split =======================
__global__ void __launch_bounds__(256)
split5(const float* __restrict__ X, const float* __restrict__ Wq,
       const float* __restrict__ Wk, const float* __restrict__ Wv,
       const float* __restrict__ Wo) {
    const float* src;
    __nv_bfloat16 *hi, *lo;
    switch (blockIdx.z) {
        case 0: src = X;  hi = g_Xhi;    lo = g_Xlo;    break;
        case 1: src = Wq; hi = g_Whi[0]; lo = g_Wlo[0]; break;
        case 2: src = Wk; hi = g_Whi[1]; lo = g_Wlo[1]; break;
        case 3: src = Wv; hi = g_Whi[2]; lo = g_Wlo[2]; break;
        default: src = Wo; hi = g_Whi[3]; lo = g_Wlo[3]; break;
    }
    size_t i4 = ((size_t)blockIdx.x * 256 + threadIdx.x) * 4;
    float4 v = *(const float4*)(src + i4);
    float f[4] = {v.x, v.y, v.z, v.w};
    ushort4 h4, l4;
    unsigned short* hp = &h4.x;
    unsigned short* lp = &l4.x;
#pragma unroll
    for (int k = 0; k < 4; k++) {
        __nv_bfloat16 bh, bl;
        split2(f[k], bh, bl);
        hp[k] = __bfloat16_as_ushort(bh);
        lp[k] = __bfloat16_as_ushort(bl);
    }
    *(ushort4*)(hi + i4) = h4;
    *(ushort4*)(lo + i4) = l4;
}

// ======================= HMMA bf16-split GEMM (cp.async pipelined) =======================
// C = A @ W^T. CTA 128x128, BK=32, 2-stage double buffer.
// MODE: 0 = fp32 out [M,HID]; 1 = Q bf16 hi/lo scaled 1/8; 2 = K bf16; 3 = V bf16 transposed.
#define GSTR 40                 // smem row stride (bf16 elems) = 80B
#define STAGE_BYTES 40960       // 4 matrices * 128*40*2
#define GEMM_SMEM (2 * STAGE_BYTES)

template <int MODE>
__device__ __forceinline__ void hmma_gemm_body(
    const __nv_bfloat16* __restrict__ Ahi, const __nv_bfloat16* __restrict__ Alo,
    const __nv_bfloat16* __restrict__ Bhi, const __nv_bfloat16* __restrict__ Blo,
    float* __restrict__ Cf, __nv_bfloat16* __restrict__ Chi,
    __nv_bfloat16* __restrict__ Clo)
{
    extern __shared__ char dsm[];
    const uint32_t sb = smem_u32(dsm);

    const int tid = threadIdx.x;
    const int wid = tid >> 5, lane = tid & 31;
    const int warp_m = (wid >> 2) * 64;
    const int warp_n = (wid & 3) * 32;
    const int m0 = blockIdx.y * 128, n0 = blockIdx.x * 128;

    const int lr = tid >> 2;
    const int seg = tid & 3;

    const uint32_t a_row = (lane & 15);
    const uint32_t a_koff = (lane >> 4) * 8;
    const uint32_t b_row = (lane & 7);
    const uint32_t b_koff = ((lane >> 3) & 1) * 8;

    float acc[4][4][4] = {};

    auto load_chunk = [&](int k0, int s) {
        const uint32_t st = sb + s * STAGE_BYTES;
#pragma unroll
        for (int p = 0; p < 2; p++) {
            const int r = p * 64 + lr;
            const uint32_t so = (uint32_t)(r * 80 + seg * 16);
            const size_t ga = (size_t)(m0 + r) * HID + k0 + seg * 8;
            const size_t gb = (size_t)(n0 + r) * HID + k0 + seg * 8;
            CP16(st + so,         Ahi + ga);
            CP16(st + 10240 + so, Alo + ga);
            CP16(st + 20480 + so, Bhi + gb);
            CP16(st + 30720 + so, Blo + gb);
        }
    };

    load_chunk(0, 0);
    CP_COMMIT;

    for (int c = 0; c < HID / 32; c++) {
        CP_WAIT0;
        __syncthreads();
        if (c < HID / 32 - 1) {
            load_chunk((c + 1) * 32, (c + 1) & 1);
            CP_COMMIT;
        }
        const uint32_t st = sb + (c & 1) * STAGE_BYTES;

#pragma unroll
        for (int kk = 0; kk < 32; kk += 16) {
            uint32_t ahi[4][4], alo[4][4], bhi[4][2], blo[4][2];
#pragma unroll
            for (int mi = 0; mi < 4; mi++) {
                const uint32_t off =
                    (uint32_t)((warp_m + mi * 16 + a_row) * GSTR + kk + a_koff) * 2;
                ldsm_x4(ahi[mi], st + off);
                ldsm_x4(alo[mi], st + 10240 + off);
            }
#pragma unroll
            for (int ni = 0; ni < 4; ni++) {
                const uint32_t off =
                    (uint32_t)((warp_n + ni * 8 + b_row) * GSTR + kk + b_koff) * 2;
                ldsm_x2(bhi[ni], st + 20480 + off);
                ldsm_x2(blo[ni], st + 30720 + off);
            }
#pragma unroll
            for (int mi = 0; mi < 4; mi++)
#pragma unroll
                for (int ni = 0; ni < 4; ni++) {
                    mma16816(acc[mi][ni], ahi[mi], bhi[ni]);
                    mma16816(acc[mi][ni], ahi[mi], blo[ni]);
                    mma16816(acc[mi][ni], alo[mi], bhi[ni]);
                }
        }
    }

    // epilogue
    const int tr = lane >> 2;
    const int tc = (lane & 3) * 2;
#pragma unroll
    for (int mi = 0; mi < 4; mi++) {
#pragma unroll
        for (int ni = 0; ni < 4; ni++) {
            const int col = n0 + warp_n + ni * 8 + tc;
#pragma unroll
            for (int half = 0; half < 2; half++) {
                const int row = m0 + warp_m + mi * 16 + half * 8 + tr;
                float v0 = acc[mi][ni][half * 2];
                float v1 = acc[mi][ni][half * 2 + 1];
                if (MODE == 0) {
                    *(float2*)(Cf + (size_t)row * HID + col) = make_float2(v0, v1);
                } else {
                    const int b = row >> 10, l = row & (SEQ - 1);
                    const int h = col >> 6, d = col & 63;
                    if (MODE == 1) { v0 *= 0.125f; v1 *= 0.125f; }
                    __nv_bfloat16 h0, l0, h1, l1;
                    split2(v0, h0, l0);
                    split2(v1, h1, l1);
                    if (MODE == 3) {
                        const size_t base = ((size_t)b * NH + h) * HD;
                        Chi[(base + d) * SEQ + l] = h0;
                        Chi[(base + d + 1) * SEQ + l] = h1;
                        Clo[(base + d) * SEQ + l] = l0;
                        Clo[(base + d + 1) * SEQ + l] = l1;
                    } else {
                        const size_t adr = (((size_t)b * NH + h) * SEQ + l) * HD + d;
                        *(__nv_bfloat162*)(Chi + adr) = __nv_bfloat162(h0, h1);
                        *(__nv_bfloat162*)(Clo + adr) = __nv_bfloat162(l0, l1);
                    }
                }
            }
        }
    }
}

__global__ void __launch_bounds__(256, 2) qkv_mma() {
    if (blockIdx.z == 0)
        hmma_gemm_body<1>(g_Xhi, g_Xlo, g_Whi[0], g_Wlo[0], nullptr, g_Qhi, g_Qlo);
    else if (blockIdx.z == 1)
        hmma_gemm_body<2>(g_Xhi, g_Xlo, g_Whi[1], g_Wlo[1], nullptr, g_Khi, g_Klo);
    else
        hmma_gemm_body<3>(g_Xhi, g_Xlo, g_Whi[2], g_Wlo[2], nullptr, g_Vthi, g_Vtlo);
}

__global__ void __launch_bounds__(256, 2) out_mma(float* Out) {
    hmma_gemm_body<0>(g_Ohi, g_Olo, g_Whi[3], g_Wlo[3], Out, nullptr, nullptr);
}

// ======================= stick-breaking attention (HMMA) =======================
// Per CTA: 64 queries x full head. 128 threads = 4 warps, warp m-rows 16.
// z = (Q/8) K^T via bf16 3-term HMMA; sigmoid+mask; per-row suffix-product scan;
// att (bf16 split) @ V via HMMA with fp32 O accumulators.
#define ASTR 72                  // bf16 smem row stride (144B)
#define oSS  0                   // fp32 [64][66]  (overlays Q region after frags read)
#define oQHI 0
#define oQLO 9216
#define oKHI 18432
#define oKLO 27648
#define oVHI 36864
#define oVLO 46080
#define oAHI 55296
#define oALO 64512
#define ATT_SMEM 73728

__global__ void __launch_bounds__(128, 2) sba_attn()
{
    extern __shared__ char dsm[];
    const uint32_t sb = smem_u32(dsm);

    const int tid = threadIdx.x;
    const int wid = tid >> 5, lane = tid & 31;
    const int warp_m = wid * 16;
    const int ti = (gridDim.x - 1) - blockIdx.x;   // heavy blocks first
    const int bh = blockIdx.y;
    const int i0 = ti * 64;

    const size_t base = (size_t)bh * SEQ * HD;
    const __nv_bfloat16* Qhi_g = g_Qhi + base + (size_t)i0 * HD;
    const __nv_bfloat16* Qlo_g = g_Qlo + base + (size_t)i0 * HD;
    const __nv_bfloat16* Khi_g = g_Khi + base;
    const __nv_bfloat16* Klo_g = g_Klo + base;
    const __nv_bfloat16* Vthi_g = g_Vthi + base;   // [d][l]
    const __nv_bfloat16* Vtlo_g = g_Vtlo + base;

    // ---- load Q tile (64x64 bf16 hi/lo) ----
#pragma unroll
    for (int t = 0; t < 4; t++) {
        const int flat = t * 128 + tid;
        const int row = flat >> 3, seg = flat & 7;
        const uint32_t off = (uint32_t)(row * 144 + seg * 16);
        CP16(sb + oQHI + off, Qhi_g + row * HD + seg * 8);
        CP16(sb + oQLO + off, Qlo_g + row * HD + seg * 8);
    }
    CP_COMMIT;
    CP_WAIT0;
    __syncthreads();

    // ---- Q A-fragments (held in regs for the whole kernel) ----
    const uint32_t a_row = lane & 15;
    const uint32_t a_koff = (lane >> 4) * 8;
    const uint32_t b_row = lane & 7;
    const uint32_t b_koff = ((lane >> 3) & 1) * 8;

    uint32_t qhi[4][4], qlo[4][4];
#pragma unroll
    for (int kk = 0; kk < 4; kk++) {
        const uint32_t off =
            (uint32_t)((warp_m + a_row) * 144 + (kk * 16 + a_koff) * 2);
        ldsm_x4(qhi[kk], sb + oQHI + off);
        ldsm_x4(qlo[kk], sb + oQLO + off);
    }

    float oacc[8][4] = {};
    float accp = 1.0f;
    const int r = lane >> 2;
    const int c2 = (lane & 3) * 2;

    for (int tj = ti; tj >= 0; tj--) {
        const int j0 = tj * 64;
        __syncthreads();   // previous tile fully consumed (also: Q ldsm done)

        // ---- load K [j][d] and Vt [d][j0+j] tiles ----
#pragma unroll
        for (int t = 0; t < 4; t++) {
            const int flat = t * 128 + tid;
            const int row = flat >> 3, seg = flat & 7;
            const uint32_t off = (uint32_t)(row * 144 + seg * 16);
            CP16(sb + oKHI + off, Khi_g + (size_t)(j0 + row) * HD + seg * 8);
            CP16(sb + oKLO + off, Klo_g + (size_t)(j0 + row) * HD + seg * 8);
            CP16(sb + oVHI + off, Vthi_g + (size_t)row * SEQ + j0 + seg * 8);
            CP16(sb + oVLO + off, Vtlo_g + (size_t)row * SEQ + j0 + seg * 8);
        }
        CP_COMMIT;
        CP_WAIT0;
        __syncthreads();

        // ---- z = (Q/8) K^T ----
        float zacc[8][4] = {};
#pragma unroll
        for (int kk = 0; kk < 4; kk++) {
            uint32_t bh_[8][2], bl_[8][2];
#pragma unroll
            for (int nt = 0; nt < 8; nt++) {
                const uint32_t off =
                    (uint32_t)((nt * 8 + b_row) * 144 + (kk * 16 + b_koff) * 2);
                ldsm_x2(bh_[nt], sb + oKHI + off);
                ldsm_x2(bl_[nt], sb + oKLO + off);
            }
#pragma unroll
            for (int nt = 0; nt < 8; nt++) {
                mma16816(zacc[nt], qhi[kk], bh_[nt]);
                mma16816(zacc[nt], qhi[kk], bl_[nt]);
                mma16816(zacc[nt], qlo[kk], bh_[nt]);
            }
        }

        // ---- sigmoid + causal mask -> Ss[i][j] (fp32) ----
        const bool diag = (tj == ti);
        float* ssp = (float*)(dsm + oSS);
#pragma unroll
        for (int nt = 0; nt < 8; nt++) {
#pragma unroll
            for (int half = 0; half < 2; half++) {
                const int i_loc = warp_m + half * 8 + r;
                float sv0, sv1;
                {
                    const float zv = zacc[nt][half * 2];
                    sv0 = __fdividef(1.0f, 1.0f + __expf(-zv));
                    if (diag && (nt * 8 + c2) >= i_loc) sv0 = 0.0f;
                }
                {
                    const float zv = zacc[nt][half * 2 + 1];
                    sv1 = __fdividef(1.0f, 1.0f + __expf(-zv));
                    if (diag && (nt * 8 + c2 + 1) >= i_loc) sv1 = 0.0f;
                }
                *(float2*)(ssp + i_loc * 66 + nt * 8 + c2) = make_float2(sv0, sv1);
            }
        }
        __syncthreads();

        // ---- per-row suffix-product scan, emit att as bf16 hi/lo ----
        if (tid < 64) {
            float acc = accp;
            const float* ssr = (float*)(dsm + oSS) + tid * 66;
            __nv_bfloat16* ah = (__nv_bfloat16*)(dsm + oAHI) + tid * ASTR;
            __nv_bfloat16* al = (__nv_bfloat16*)(dsm + oALO) + tid * ASTR;
#pragma unroll
            for (int j = 63; j >= 0; j--) {
                const float sv = ssr[j];
                const float att = sv * acc;
                acc -= att;                       // acc *= (1 - sv)
                __nv_bfloat16 h, l;
                split2(att, h, l);
                ah[j] = h;
                al[j] = l;
            }
            accp = acc;
        }
        __syncthreads();

        // ---- O += att @ V ----
#pragma unroll
        for (int kk = 0; kk < 4; kk++) {
            uint32_t ahv[4], alv[4];
            const uint32_t offA =
                (uint32_t)((warp_m + a_row) * 144 + (kk * 16 + a_koff) * 2);
            ldsm_x4(ahv, sb + oAHI + offA);
            ldsm_x4(alv, sb + oALO + offA);
#pragma unroll
            for (int nt = 0; nt < 8; nt++) {
                uint32_t vh[2], vl[2];
                const uint32_t off =
                    (uint32_t)((nt * 8 + b_row) * 144 + (kk * 16 + b_koff) * 2);
                ldsm_x2(vh, sb + oVHI + off);
                ldsm_x2(vl, sb + oVLO + off);
                mma16816(oacc[nt], ahv, vh);
                mma16816(oacc[nt], ahv, vl);
                mma16816(oacc[nt], alv, vh);
            }
        }
    }

    // ---- epilogue: write O as bf16 hi/lo, flat [b, l, h*64+d] ----
    const int b = bh >> 5, h = bh & 31;
#pragma unroll
    for (int nt = 0; nt < 8; nt++) {
#pragma unroll
        for (int half = 0; half < 2; half++) {
            const int i = i0 + warp_m + half * 8 + r;
            const int d = nt * 8 + c2;
            __nv_bfloat16 h0, l0, h1, l1;
            split2(oacc[nt][half * 2], h0, l0);
            split2(oacc[nt][half * 2 + 1], h1, l1);
            const size_t adr = ((size_t)b * SEQ + i) * HID + h * HD + d;
            *(__nv_bfloat162*)(g_Ohi + adr) = __nv_bfloat162(h0, h1);
            *(__nv_bfloat162*)(g_Olo + adr) = __nv_bfloat162(l0, l1);
        }
    }
}

// ======================= launch =======================
extern "C" void kernel_launch(void* const* d_in, const int* in_sizes, int n_in,
                              void* d_out, int out_size)
{
    const float* X  = (const float*)d_in[0];
    const float* Wq = (const float*)d_in[1];
    const float* Wk = (const float*)d_in[2];
    const float* Wv = (const float*)d_in[3];
    const float* Wo = (const float*)d_in[4];
    float* Out = (float*)d_out;

    cudaFuncSetAttribute(qkv_mma, cudaFuncAttributeMaxDynamicSharedMemorySize,
                         GEMM_SMEM);
    cudaFuncSetAttribute(out_mma, cudaFuncAttributeMaxDynamicSharedMemorySize,
                         GEMM_SMEM);
    cudaFuncSetAttribute(sba_attn, cudaFuncAttributeMaxDynamicSharedMemorySize,
                         ATT_SMEM);

    split5<<<dim3((HID * HID / 4) / 256, 1, 5), 256>>>(X, Wq, Wk, Wv, Wo);
    qkv_mma<<<dim3(HID / 128, (NBATCH * SEQ) / 128, 3), 256, GEMM_SMEM>>>();
    sba_attn<<<dim3(SEQ / 64, NBATCH * NH), 128, ATT_SMEM>>>();
    out_mma<<<dim3(HID / 128, (NBATCH * SEQ) / 128, 1), 256, GEMM_SMEM>>>(Out);
}

// round 5
// speedup vs baseline: 2.9394x; 1.0003x over previous
#include <cuda_runtime.h>
#include <cuda_bf16.h>
#include <cstdint>

#define NBATCH 2
#define SEQ    1024
#define HID    2048
#define NH     32
#define HD     64

// ======================= scratch =======================
#define QKV_ELEMS ((size_t)NBATCH * NH * SEQ * HD)
__device__ __nv_bfloat16 g_Xhi[(size_t)NBATCH * SEQ * HID];
__device__ __nv_bfloat16 g_Xlo[(size_t)NBATCH * SEQ * HID];
__device__ __nv_bfloat16 g_Whi[4][(size_t)HID * HID];   // q,k,v,o
__device__ __nv_bfloat16 g_Wlo[4][(size_t)HID * HID];
__device__ __nv_bfloat16 g_Qhi[QKV_ELEMS], g_Qlo[QKV_ELEMS];   // [b,h,l,d], pre-scaled 1/8
__device__ __nv_bfloat16 g_Khi[QKV_ELEMS], g_Klo[QKV_ELEMS];   // [b,h,l,d]
__device__ __nv_bfloat16 g_Vthi[QKV_ELEMS], g_Vtlo[QKV_ELEMS]; // [b,h,d,l] transposed
__device__ __nv_bfloat16 g_Ohi[(size_t)NBATCH * SEQ * HID];
__device__ __nv_bfloat16 g_Olo[(size_t)NBATCH * SEQ * HID];

// ======================= helpers =======================
__device__ __forceinline__ uint32_t smem_u32(const void* p) {
    uint32_t a;
    asm("{ .reg .u64 t; cvta.to.shared.u64 t, %1; cvt.u32.u64 %0, t; }"
        : "=r"(a) : "l"(p));
    return a;
}
__device__ __forceinline__ void ldsm_x4(uint32_t* r, uint32_t addr) {
    asm volatile("ldmatrix.sync.aligned.m8n8.x4.shared.b16 {%0,%1,%2,%3}, [%4];"
                 : "=r"(r[0]), "=r"(r[1]), "=r"(r[2]), "=r"(r[3]) : "r"(addr));
}
__device__ __forceinline__ void ldsm_x2(uint32_t* r, uint32_t addr) {
    asm volatile("ldmatrix.sync.aligned.m8n8.x2.shared.b16 {%0,%1}, [%2];"
                 : "=r"(r[0]), "=r"(r[1]) : "r"(addr));
}
// NOTE: non-volatile on purpose — register-only op, lets ptxas interleave
// independent fragments to hide HMMA latency.
__device__ __forceinline__ void mma16816(float* c, const uint32_t* a,
                                         const uint32_t* b) {
    asm("mma.sync.aligned.m16n8k16.row.col.f32.bf16.bf16.f32 "
        "{%0,%1,%2,%3}, {%4,%5,%6,%7}, {%8,%9}, {%0,%1,%2,%3};"
        : "+f"(c[0]), "+f"(c[1]), "+f"(c[2]), "+f"(c[3])
        : "r"(a[0]), "r"(a[1]), "r"(a[2]), "r"(a[3]), "r"(b[0]), "r"(b[1]));
}
#define CP16(dst, src) \
    asm volatile("cp.async.cg.shared.global [%0], [%1], 16;" \
                 :: "r"(dst), "l"(src) : "memory")
#define CP_COMMIT asm volatile("cp.async.commit_group;" ::: "memory")
#define CP_WAIT0  asm volatile("cp.async.wait_group 0;" ::: "memory")

__device__ __forceinline__ void split2(float v, __nv_bfloat16& h, __nv_bfloat16& l) {
    h = __float2bfloat16_rn(v);
    l = __float2bfloat16_rn(v - __bfloat162float(h));
}

// ======================= fp32 -> bf16 hi/lo split =======================
__global__ void __launch_bounds__(256)
split5(const float* __restrict__ X, const float* __restrict__ Wq,
       const float* __restrict__ Wk, const float* __restrict__ Wv,
       const float* __restrict__ Wo) {
    const float* src;
    __nv_bfloat16 *hi, *lo;
    switch (blockIdx.z) {
        case 0: src = X;  hi = g_Xhi;    lo = g_Xlo;    break;
        case 1: src = Wq; hi = g_Whi[0]; lo = g_Wlo[0]; break;
        case 2: src = Wk; hi = g_Whi[1]; lo = g_Wlo[1]; break;
        case 3: src = Wv; hi = g_Whi[2]; lo = g_Wlo[2]; break;
        default: src = Wo; hi = g_Whi[3]; lo = g_Wlo[3]; break;
    }
    size_t i4 = ((size_t)blockIdx.x * 256 + threadIdx.x) * 4;
    float4 v = *(const float4*)(src + i4);
    float f[4] = {v.x, v.y, v.z, v.w};
    ushort4 h4, l4;
    unsigned short* hp = &h4.x;
    unsigned short* lp = &l4.x;
#pragma unroll
    for (int k = 0; k < 4; k++) {
        __nv_bfloat16 bh, bl;
        split2(f[k], bh, bl);
        hp[k] = __bfloat16_as_ushort(bh);
        lp[k] = __bfloat16_as_ushort(bl);
    }
    *(ushort4*)(hi + i4) = h4;
    *(ushort4*)(lo + i4) = l4;
}

// ======================= HMMA bf16-split GEMM (cp.async pipelined) =======================
#define GSTR 40                 // smem row stride (bf16 elems) = 80B
#define STAGE_BYTES 40960       // 4 matrices * 128*40*2
#define GEMM_SMEM (2 * STAGE_BYTES)

template <int MODE>
__device__ __forceinline__ void hmma_gemm_body(
    const __nv_bfloat16* __restrict__ Ahi, const __nv_bfloat16* __restrict__ Alo,
    const __nv_bfloat16* __restrict__ Bhi, const __nv_bfloat16* __restrict__ Blo,
    float* __restrict__ Cf, __nv_bfloat16* __restrict__ Chi,
    __nv_bfloat16* __restrict__ Clo)
{
    extern __shared__ char dsm[];
    const uint32_t sb = smem_u32(dsm);

    const int tid = threadIdx.x;
    const int wid = tid >> 5, lane = tid & 31;
    const int warp_m = (wid >> 2) * 64;
    const int warp_n = (wid & 3) * 32;
    const int m0 = blockIdx.y * 128, n0 = blockIdx.x * 128;

    const int lr = tid >> 2;
    const int seg = tid & 3;

    const uint32_t a_row = (lane & 15);
    const uint32_t a_koff = (lane >> 4) * 8;
    const uint32_t b_row = (lane & 7);
    const uint32_t b_koff = ((lane >> 3) & 1) * 8;

    float acc[4][4][4] = {};

    auto load_chunk = [&](int k0, int s) {
        const uint32_t st = sb + s * STAGE_BYTES;
#pragma unroll
        for (int p = 0; p < 2; p++) {
            const int r = p * 64 + lr;
            const uint32_t so = (uint32_t)(r * 80 + seg * 16);
            const size_t ga = (size_t)(m0 + r) * HID + k0 + seg * 8;
            const size_t gb = (size_t)(n0 + r) * HID + k0 + seg * 8;
            CP16(st + so,         Ahi + ga);
            CP16(st + 10240 + so, Alo + ga);
            CP16(st + 20480 + so, Bhi + gb);
            CP16(st + 30720 + so, Blo + gb);
        }
    };

    load_chunk(0, 0);
    CP_COMMIT;

    for (int c = 0; c < HID / 32; c++) {
        CP_WAIT0;
        __syncthreads();
        if (c < HID / 32 - 1) {
            load_chunk((c + 1) * 32, (c + 1) & 1);
            CP_COMMIT;
        }
        const uint32_t st = sb + (c & 1) * STAGE_BYTES;

#pragma unroll
        for (int kk = 0; kk < 32; kk += 16) {
            uint32_t ahi[4][4], alo[4][4], bhi[4][2], blo[4][2];
#pragma unroll
            for (int mi = 0; mi < 4; mi++) {
                const uint32_t off =
                    (uint32_t)((warp_m + mi * 16 + a_row) * GSTR + kk + a_koff) * 2;
                ldsm_x4(ahi[mi], st + off);
                ldsm_x4(alo[mi], st + 10240 + off);
            }
#pragma unroll
            for (int ni = 0; ni < 4; ni++) {
                const uint32_t off =
                    (uint32_t)((warp_n + ni * 8 + b_row) * GSTR + kk + b_koff) * 2;
                ldsm_x2(bhi[ni], st + 20480 + off);
                ldsm_x2(blo[ni], st + 30720 + off);
            }
            // term-major ordering: 16 independent MMAs between accumulator reuse
#pragma unroll
            for (int mi = 0; mi < 4; mi++)
#pragma unroll
                for (int ni = 0; ni < 4; ni++)
                    mma16816(acc[mi][ni], ahi[mi], bhi[ni]);
#pragma unroll
            for (int mi = 0; mi < 4; mi++)
#pragma unroll
                for (int ni = 0; ni < 4; ni++)
                    mma16816(acc[mi][ni], ahi[mi], blo[ni]);
#pragma unroll
            for (int mi = 0; mi < 4; mi++)
#pragma unroll
                for (int ni = 0; ni < 4; ni++)
                    mma16816(acc[mi][ni], alo[mi], bhi[ni]);
        }
    }

    // epilogue
    const int tr = lane >> 2;
    const int tc = (lane & 3) * 2;
#pragma unroll
    for (int mi = 0; mi < 4; mi++) {
#pragma unroll
        for (int ni = 0; ni < 4; ni++) {
            const int col = n0 + warp_n + ni * 8 + tc;
#pragma unroll
            for (int half = 0; half < 2; half++) {
                const int row = m0 + warp_m + mi * 16 + half * 8 + tr;
                float v0 = acc[mi][ni][half * 2];
                float v1 = acc[mi][ni][half * 2 + 1];
                if (MODE == 0) {
                    *(float2*)(Cf + (size_t)row * HID + col) = make_float2(v0, v1);
                } else {
                    const int b = row >> 10, l = row & (SEQ - 1);
                    const int h = col >> 6, d = col & 63;
                    if (MODE == 1) { v0 *= 0.125f; v1 *= 0.125f; }
                    __nv_bfloat16 h0, l0, h1, l1;
                    split2(v0, h0, l0);
                    split2(v1, h1, l1);
                    if (MODE == 3) {
                        const size_t base = ((size_t)b * NH + h) * HD;
                        Chi[(base + d) * SEQ + l] = h0;
                        Chi[(base + d + 1) * SEQ + l] = h1;
                        Clo[(base + d) * SEQ + l] = l0;
                        Clo[(base + d + 1) * SEQ + l] = l1;
                    } else {
                        const size_t adr = (((size_t)b * NH + h) * SEQ + l) * HD + d;
                        *(__nv_bfloat162*)(Chi + adr) = __nv_bfloat162(h0, h1);
                        *(__nv_bfloat162*)(Clo + adr) = __nv_bfloat162(l0, l1);
                    }
                }
            }
        }
    }
}

__global__ void __launch_bounds__(256, 2) qkv_mma() {
    if (blockIdx.z == 0)
        hmma_gemm_body<1>(g_Xhi, g_Xlo, g_Whi[0], g_Wlo[0], nullptr, g_Qhi, g_Qlo);
    else if (blockIdx.z == 1)
        hmma_gemm_body<2>(g_Xhi, g_Xlo, g_Whi[1], g_Wlo[1], nullptr, g_Khi, g_Klo);
    else
        hmma_gemm_body<3>(g_Xhi, g_Xlo, g_Whi[2], g_Wlo[2], nullptr, g_Vthi, g_Vtlo);
}

__global__ void __launch_bounds__(256, 2) out_mma(float* Out) {
    hmma_gemm_body<0>(g_Ohi, g_Olo, g_Whi[3], g_Wlo[3], Out, nullptr, nullptr);
}

// ======================= stick-breaking attention (HMMA) =======================
#define ASTR 72                  // bf16 smem row stride (144B)
#define oSS  0                   // fp32 [64][66]  (overlays Q region after frags read)
#define oQHI 0
#define oQLO 9216
#define oKHI 18432
#define oKLO 27648
#define oVHI 36864
#define oVLO 46080
#define oAHI 55296
#define oALO 64512
#define ATT_SMEM 73728

__global__ void __launch_bounds__(128, 2) sba_attn()
{
    extern __shared__ char dsm[];
    const uint32_t sb = smem_u32(dsm);

    const int tid = threadIdx.x;
    const int wid = tid >> 5, lane = tid & 31;
    const int warp_m = wid * 16;
    const int ti = (gridDim.x - 1) - blockIdx.x;   // heavy blocks first
    const int bh = blockIdx.y;
    const int i0 = ti * 64;

    const size_t base = (size_t)bh * SEQ * HD;
    const __nv_bfloat16* Qhi_g = g_Qhi + base + (size_t)i0 * HD;
    const __nv_bfloat16* Qlo_g = g_Qlo + base + (size_t)i0 * HD;
    const __nv_bfloat16* Khi_g = g_Khi + base;
    const __nv_bfloat16* Klo_g = g_Klo + base;
    const __nv_bfloat16* Vthi_g = g_Vthi + base;   // [d][l]
    const __nv_bfloat16* Vtlo_g = g_Vtlo + base;

    // ---- load Q tile (64x64 bf16 hi/lo) ----
#pragma unroll
    for (int t = 0; t < 4; t++) {
        const int flat = t * 128 + tid;
        const int row = flat >> 3, seg = flat & 7;
        const uint32_t off = (uint32_t)(row * 144 + seg * 16);
        CP16(sb + oQHI + off, Qhi_g + row * HD + seg * 8);
        CP16(sb + oQLO + off, Qlo_g + row * HD + seg * 8);
    }
    CP_COMMIT;
    CP_WAIT0;
    __syncthreads();

    const uint32_t a_row = lane & 15;
    const uint32_t a_koff = (lane >> 4) * 8;
    const uint32_t b_row = lane & 7;
    const uint32_t b_koff = ((lane >> 3) & 1) * 8;

    uint32_t qhi[4][4], qlo[4][4];
#pragma unroll
    for (int kk = 0; kk < 4; kk++) {
        const uint32_t off =
            (uint32_t)((warp_m + a_row) * 144 + (kk * 16 + a_koff) * 2);
        ldsm_x4(qhi[kk], sb + oQHI + off);
        ldsm_x4(qlo[kk], sb + oQLO + off);
    }

    float oacc[8][4] = {};
    float accp = 1.0f;
    const int r = lane >> 2;
    const int c2 = (lane & 3) * 2;

    for (int tj = ti; tj >= 0; tj--) {
        const int j0 = tj * 64;
        __syncthreads();   // previous tile fully consumed (also: Q ldsm done)

        // ---- load K [j][d] and Vt [d][j0+j] tiles ----
#pragma unroll
        for (int t = 0; t < 4; t++) {
            const int flat = t * 128 + tid;
            const int row = flat >> 3, seg = flat & 7;
            const uint32_t off = (uint32_t)(row * 144 + seg * 16);
            CP16(sb + oKHI + off, Khi_g + (size_t)(j0 + row) * HD + seg * 8);
            CP16(sb + oKLO + off, Klo_g + (size_t)(j0 + row) * HD + seg * 8);
            CP16(sb + oVHI + off, Vthi_g + (size_t)row * SEQ + j0 + seg * 8);
            CP16(sb + oVLO + off, Vtlo_g + (size_t)row * SEQ + j0 + seg * 8);
        }
        CP_COMMIT;
        CP_WAIT0;
        __syncthreads();

        // ---- z = (Q/8) K^T, term-major (8 independent accs per term) ----
        float zacc[8][4] = {};
#pragma unroll
        for (int kk = 0; kk < 4; kk++) {
            uint32_t bh_[8][2], bl_[8][2];
#pragma unroll
            for (int nt = 0; nt < 8; nt++) {
                const uint32_t off =
                    (uint32_t)((nt * 8 + b_row) * 144 + (kk * 16 + b_koff) * 2);
                ldsm_x2(bh_[nt], sb + oKHI + off);
                ldsm_x2(bl_[nt], sb + oKLO + off);
            }
#pragma unroll
            for (int nt = 0; nt < 8; nt++)
                mma16816(zacc[nt], qhi[kk], bh_[nt]);
#pragma unroll
            for (int nt = 0; nt < 8; nt++)
                mma16816(zacc[nt], qhi[kk], bl_[nt]);
#pragma unroll
            for (int nt = 0; nt < 8; nt++)
                mma16816(zacc[nt], qlo[kk], bh_[nt]);
        }

        // ---- sigmoid + causal mask -> Ss[i][j] (fp32) ----
        const bool diag = (tj == ti);
        float* ssp = (float*)(dsm + oSS);
#pragma unroll
        for (int nt = 0; nt < 8; nt++) {
#pragma unroll
            for (int half = 0; half < 2; half++) {
                const int i_loc = warp_m + half * 8 + r;
                float sv0, sv1;
                {
                    const float zv = zacc[nt][half * 2];
                    sv0 = __fdividef(1.0f, 1.0f + __expf(-zv));
                    if (diag && (nt * 8 + c2) >= i_loc) sv0 = 0.0f;
                }
                {
                    const float zv = zacc[nt][half * 2 + 1];
                    sv1 = __fdividef(1.0f, 1.0f + __expf(-zv));
                    if (diag && (nt * 8 + c2 + 1) >= i_loc) sv1 = 0.0f;
                }
                *(float2*)(ssp + i_loc * 66 + nt * 8 + c2) = make_float2(sv0, sv1);
            }
        }
        __syncthreads();

        // ---- per-row suffix-product scan, emit att as bf16 hi/lo ----
        if (tid < 64) {
            float acc = accp;
            const float* ssr = (float*)(dsm + oSS) + tid * 66;
            __nv_bfloat16* ah = (__nv_bfloat16*)(dsm + oAHI) + tid * ASTR;
            __nv_bfloat16* al = (__nv_bfloat16*)(dsm + oALO) + tid * ASTR;
#pragma unroll
            for (int j = 63; j >= 0; j--) {
                const float sv = ssr[j];
                const float att = sv * acc;
                acc -= att;                       // acc *= (1 - sv)
                __nv_bfloat16 h, l;
                split2(att, h, l);
                ah[j] = h;
                al[j] = l;
            }
            accp = acc;
        }
        __syncthreads();

        // ---- O += att @ V, term-major ----
#pragma unroll
        for (int kk = 0; kk < 4; kk++) {
            uint32_t ahv[4], alv[4];
            const uint32_t offA =
                (uint32_t)((warp_m + a_row) * 144 + (kk * 16 + a_koff) * 2);
            ldsm_x4(ahv, sb + oAHI + offA);
            ldsm_x4(alv, sb + oALO + offA);
            uint32_t vh[8][2], vl[8][2];
#pragma unroll
            for (int nt = 0; nt < 8; nt++) {
                const uint32_t off =
                    (uint32_t)((nt * 8 + b_row) * 144 + (kk * 16 + b_koff) * 2);
                ldsm_x2(vh[nt], sb + oVHI + off);
                ldsm_x2(vl[nt], sb + oVLO + off);
            }
#pragma unroll
            for (int nt = 0; nt < 8; nt++)
                mma16816(oacc[nt], ahv, vh[nt]);
#pragma unroll
            for (int nt = 0; nt < 8; nt++)
                mma16816(oacc[nt], ahv, vl[nt]);
#pragma unroll
            for (int nt = 0; nt < 8; nt++)
                mma16816(oacc[nt], alv, vh[nt]);
        }
    }

    // ---- epilogue: write O as bf16 hi/lo, flat [b, l, h*64+d] ----
    const int b = bh >> 5, h = bh & 31;
#pragma unroll
    for (int nt = 0; nt < 8; nt++) {
#pragma unroll
        for (int half = 0; half < 2; half++) {
            const int i = i0 + warp_m + half * 8 + r;
            const int d = nt * 8 + c2;
            __nv_bfloat16 h0, l0, h1, l1;
            split2(oacc[nt][half * 2], h0, l0);
            split2(oacc[nt][half * 2 + 1], h1, l1);
            const size_t adr = ((size_t)b * SEQ + i) * HID + h * HD + d;
            *(__nv_bfloat162*)(g_Ohi + adr) = __nv_bfloat162(h0, h1);
            *(__nv_bfloat162*)(g_Olo + adr) = __nv_bfloat162(l0, l1);
        }
    }
}

// ======================= launch =======================
extern "C" void kernel_launch(void* const* d_in, const int* in_sizes, int n_in,
                              void* d_out, int out_size)
{
    const float* X  = (const float*)d_in[0];
    const float* Wq = (const float*)d_in[1];
    const float* Wk = (const float*)d_in[2];
    const float* Wv = (const float*)d_in[3];
    const float* Wo = (const float*)d_in[4];
    float* Out = (float*)d_out;

    cudaFuncSetAttribute(qkv_mma, cudaFuncAttributeMaxDynamicSharedMemorySize,
                         GEMM_SMEM);
    cudaFuncSetAttribute(out_mma, cudaFuncAttributeMaxDynamicSharedMemorySize,
                         GEMM_SMEM);
    cudaFuncSetAttribute(sba_attn, cudaFuncAttributeMaxDynamicSharedMemorySize,
                         ATT_SMEM);

    split5<<<dim3((HID * HID / 4) / 256, 1, 5), 256>>>(X, Wq, Wk, Wv, Wo);
    qkv_mma<<<dim3(HID / 128, (NBATCH * SEQ) / 128, 3), 256, GEMM_SMEM>>>();
    sba_attn<<<dim3(SEQ / 64, NBATCH * NH), 128, ATT_SMEM>>>();
    out_mma<<<dim3(HID / 128, (NBATCH * SEQ) / 128, 1), 256, GEMM_SMEM>>>(Out);
}

// round 6
// speedup vs baseline: 3.1780x; 1.0812x over previous
#include <cuda_runtime.h>
#include <cuda_bf16.h>
#include <cstdint>

#define NBATCH 2
#define SEQ    1024
#define HID    2048
#define NH     32
#define HD     64

// ======================= scratch =======================
#define QKV_ELEMS ((size_t)NBATCH * NH * SEQ * HD)
__device__ __nv_bfloat16 g_Xhi[(size_t)NBATCH * SEQ * HID];
__device__ __nv_bfloat16 g_Xlo[(size_t)NBATCH * SEQ * HID];
__device__ __nv_bfloat16 g_Whi[4][(size_t)HID * HID];   // q,k,v,o
__device__ __nv_bfloat16 g_Wlo[4][(size_t)HID * HID];
__device__ __nv_bfloat16 g_Qhi[QKV_ELEMS], g_Qlo[QKV_ELEMS];   // [b,h,l,d], pre-scaled 1/8
__device__ __nv_bfloat16 g_Khi[QKV_ELEMS], g_Klo[QKV_ELEMS];   // [b,h,l,d]
__device__ __nv_bfloat16 g_Vthi[QKV_ELEMS], g_Vtlo[QKV_ELEMS]; // [b,h,d,l] transposed
__device__ __nv_bfloat16 g_Ohi[(size_t)NBATCH * SEQ * HID];
__device__ __nv_bfloat16 g_Olo[(size_t)NBATCH * SEQ * HID];

// ======================= helpers =======================
__device__ __forceinline__ uint32_t smem_u32(const void* p) {
    uint32_t a;
    asm("{ .reg .u64 t; cvta.to.shared.u64 t, %1; cvt.u32.u64 %0, t; }"
        : "=r"(a) : "l"(p));
    return a;
}
__device__ __forceinline__ void ldsm_x4(uint32_t* r, uint32_t addr) {
    asm volatile("ldmatrix.sync.aligned.m8n8.x4.shared.b16 {%0,%1,%2,%3}, [%4];"
                 : "=r"(r[0]), "=r"(r[1]), "=r"(r[2]), "=r"(r[3]) : "r"(addr));
}
__device__ __forceinline__ void ldsm_x2(uint32_t* r, uint32_t addr) {
    asm volatile("ldmatrix.sync.aligned.m8n8.x2.shared.b16 {%0,%1}, [%2];"
                 : "=r"(r[0]), "=r"(r[1]) : "r"(addr));
}
__device__ __forceinline__ void mma16816(float* c, const uint32_t* a,
                                         const uint32_t* b) {
    asm("mma.sync.aligned.m16n8k16.row.col.f32.bf16.bf16.f32 "
        "{%0,%1,%2,%3}, {%4,%5,%6,%7}, {%8,%9}, {%0,%1,%2,%3};"
        : "+f"(c[0]), "+f"(c[1]), "+f"(c[2]), "+f"(c[3])
        : "r"(a[0]), "r"(a[1]), "r"(a[2]), "r"(a[3]), "r"(b[0]), "r"(b[1]));
}
#define CP16(dst, src) \
    asm volatile("cp.async.cg.shared.global [%0], [%1], 16;" \
                 :: "r"(dst), "l"(src) : "memory")
#define CP_COMMIT asm volatile("cp.async.commit_group;" ::: "memory")
#define CP_WAIT0  asm volatile("cp.async.wait_group 0;" ::: "memory")

__device__ __forceinline__ void split2(float v, __nv_bfloat16& h, __nv_bfloat16& l) {
    h = __float2bfloat16_rn(v);
    l = __float2bfloat16_rn(v - __bfloat162float(h));
}

// ======================= fp32 -> bf16 hi/lo split =======================
__global__ void __launch_bounds__(256)
split5(const float* __restrict__ X, const float* __restrict__ Wq,
       const float* __restrict__ Wk, const float* __restrict__ Wv,
       const float* __restrict__ Wo) {
    const float* src;
    __nv_bfloat16 *hi, *lo;
    switch (blockIdx.z) {
        case 0: src = X;  hi = g_Xhi;    lo = g_Xlo;    break;
        case 1: src = Wq; hi = g_Whi[0]; lo = g_Wlo[0]; break;
        case 2: src = Wk; hi = g_Whi[1]; lo = g_Wlo[1]; break;
        case 3: src = Wv; hi = g_Whi[2]; lo = g_Wlo[2]; break;
        default: src = Wo; hi = g_Whi[3]; lo = g_Wlo[3]; break;
    }
    size_t i4 = ((size_t)blockIdx.x * 256 + threadIdx.x) * 4;
    float4 v = *(const float4*)(src + i4);
    float f[4] = {v.x, v.y, v.z, v.w};
    ushort4 h4, l4;
    unsigned short* hp = &h4.x;
    unsigned short* lp = &l4.x;
#pragma unroll
    for (int k = 0; k < 4; k++) {
        __nv_bfloat16 bh, bl;
        split2(f[k], bh, bl);
        hp[k] = __bfloat16_as_ushort(bh);
        lp[k] = __bfloat16_as_ushort(bl);
    }
    *(ushort4*)(hi + i4) = h4;
    *(ushort4*)(lo + i4) = l4;
}

// ======================= HMMA bf16-split GEMM =======================
// CTA tile 128(M) x 256(N), BK=64, 8 warps each 64x64, 2-stage cp.async.
// MODE: 0 = fp32 out; 1 = Q bf16 scaled 1/8; 2 = K bf16; 3 = V bf16 transposed.
#define GSTR  72                 // smem row stride (bf16) = 144B
#define oAhi  0
#define oAlo  18432
#define oBhi  36864
#define oBlo  73728
#define STAGE_BYTES 110592       // A 2*18432 + B 2*36864
#define GEMM_SMEM (2 * STAGE_BYTES)

template <int MODE>
__device__ __forceinline__ void hmma_gemm_body(
    const __nv_bfloat16* __restrict__ Ahi, const __nv_bfloat16* __restrict__ Alo,
    const __nv_bfloat16* __restrict__ Bhi, const __nv_bfloat16* __restrict__ Blo,
    float* __restrict__ Cf, __nv_bfloat16* __restrict__ Chi,
    __nv_bfloat16* __restrict__ Clo)
{
    extern __shared__ char dsm[];
    const uint32_t sb = smem_u32(dsm);

    const int tid = threadIdx.x;
    const int wid = tid >> 5, lane = tid & 31;
    const int warp_m = (wid >> 2) * 64;      // 0 or 64
    const int warp_n = (wid & 3) * 64;       // 0,64,128,192
    const int m0 = blockIdx.y * 128, n0 = blockIdx.x * 256;

    const uint32_t a_row = (lane & 15);
    const uint32_t a_koff = (lane >> 4) * 8;
    const uint32_t b_row = (lane & 7);
    const uint32_t b_koff = ((lane >> 3) & 1) * 8;

    float acc[4][8][4] = {};

    auto load_chunk = [&](int k0, int s) {
        const uint32_t st = sb + s * STAGE_BYTES;
#pragma unroll
        for (int p = 0; p < 4; p++) {        // A: 128 rows x 8 segs
            const int flat = p * 256 + tid;
            const int row = flat >> 3, seg = flat & 7;
            const uint32_t so = (uint32_t)(row * 144 + seg * 16);
            const size_t ga = (size_t)(m0 + row) * HID + k0 + seg * 8;
            CP16(st + oAhi + so, Ahi + ga);
            CP16(st + oAlo + so, Alo + ga);
        }
#pragma unroll
        for (int p = 0; p < 8; p++) {        // B: 256 rows x 8 segs
            const int flat = p * 256 + tid;
            const int row = flat >> 3, seg = flat & 7;
            const uint32_t so = (uint32_t)(row * 144 + seg * 16);
            const size_t gb = (size_t)(n0 + row) * HID + k0 + seg * 8;
            CP16(st + oBhi + so, Bhi + gb);
            CP16(st + oBlo + so, Blo + gb);
        }
    };

    load_chunk(0, 0);
    CP_COMMIT;

    for (int c = 0; c < HID / 64; c++) {
        CP_WAIT0;
        __syncthreads();
        if (c < HID / 64 - 1) {
            load_chunk((c + 1) * 64, (c + 1) & 1);
            CP_COMMIT;
        }
        const uint32_t st = sb + (c & 1) * STAGE_BYTES;

#pragma unroll
        for (int kk = 0; kk < 64; kk += 16) {
            uint32_t ahi[4][4], alo[4][4];
#pragma unroll
            for (int mi = 0; mi < 4; mi++) {
                const uint32_t off =
                    (uint32_t)((warp_m + mi * 16 + a_row) * GSTR + kk + a_koff) * 2;
                ldsm_x4(ahi[mi], st + oAhi + off);
                ldsm_x4(alo[mi], st + oAlo + off);
            }
#pragma unroll
            for (int nh = 0; nh < 2; nh++) {
                uint32_t bhf[4][2], blf[4][2];
#pragma unroll
                for (int nj = 0; nj < 4; nj++) {
                    const int ni = nh * 4 + nj;
                    const uint32_t off =
                        (uint32_t)((warp_n + ni * 8 + b_row) * GSTR + kk + b_koff) * 2;
                    ldsm_x2(bhf[nj], st + oBhi + off);
                    ldsm_x2(blf[nj], st + oBlo + off);
                }
#pragma unroll
                for (int mi = 0; mi < 4; mi++)
#pragma unroll
                    for (int nj = 0; nj < 4; nj++)
                        mma16816(acc[mi][nh * 4 + nj], ahi[mi], bhf[nj]);
#pragma unroll
                for (int mi = 0; mi < 4; mi++)
#pragma unroll
                    for (int nj = 0; nj < 4; nj++)
                        mma16816(acc[mi][nh * 4 + nj], ahi[mi], blf[nj]);
#pragma unroll
                for (int mi = 0; mi < 4; mi++)
#pragma unroll
                    for (int nj = 0; nj < 4; nj++)
                        mma16816(acc[mi][nh * 4 + nj], alo[mi], bhf[nj]);
            }
        }
    }

    // epilogue
    const int tr = lane >> 2;
    const int tc = (lane & 3) * 2;
#pragma unroll
    for (int mi = 0; mi < 4; mi++) {
#pragma unroll
        for (int ni = 0; ni < 8; ni++) {
            const int col = n0 + warp_n + ni * 8 + tc;
#pragma unroll
            for (int half = 0; half < 2; half++) {
                const int row = m0 + warp_m + mi * 16 + half * 8 + tr;
                float v0 = acc[mi][ni][half * 2];
                float v1 = acc[mi][ni][half * 2 + 1];
                if (MODE == 0) {
                    *(float2*)(Cf + (size_t)row * HID + col) = make_float2(v0, v1);
                } else {
                    const int b = row >> 10, l = row & (SEQ - 1);
                    const int h = col >> 6, d = col & 63;
                    if (MODE == 1) { v0 *= 0.125f; v1 *= 0.125f; }
                    __nv_bfloat16 h0, l0, h1, l1;
                    split2(v0, h0, l0);
                    split2(v1, h1, l1);
                    if (MODE == 3) {
                        const size_t base = ((size_t)b * NH + h) * HD;
                        Chi[(base + d) * SEQ + l] = h0;
                        Chi[(base + d + 1) * SEQ + l] = h1;
                        Clo[(base + d) * SEQ + l] = l0;
                        Clo[(base + d + 1) * SEQ + l] = l1;
                    } else {
                        const size_t adr = (((size_t)b * NH + h) * SEQ + l) * HD + d;
                        *(__nv_bfloat162*)(Chi + adr) = __nv_bfloat162(h0, h1);
                        *(__nv_bfloat162*)(Clo + adr) = __nv_bfloat162(l0, l1);
                    }
                }
            }
        }
    }
}

__global__ void __launch_bounds__(256, 1) qkv_mma() {
    if (blockIdx.z == 0)
        hmma_gemm_body<1>(g_Xhi, g_Xlo, g_Whi[0], g_Wlo[0], nullptr, g_Qhi, g_Qlo);
    else if (blockIdx.z == 1)
        hmma_gemm_body<2>(g_Xhi, g_Xlo, g_Whi[1], g_Wlo[1], nullptr, g_Khi, g_Klo);
    else
        hmma_gemm_body<3>(g_Xhi, g_Xlo, g_Whi[2], g_Wlo[2], nullptr, g_Vthi, g_Vtlo);
}

__global__ void __launch_bounds__(256, 1) out_mma(float* Out) {
    hmma_gemm_body<0>(g_Ohi, g_Olo, g_Whi[3], g_Wlo[3], Out, nullptr, nullptr);
}

// ======================= stick-breaking attention (HMMA) =======================
#define ASTR 72
#define oSS  0
#define oQHI 0
#define oQLO 9216
#define oKHI 18432
#define oKLO 27648
#define oVHI 36864
#define oVLO 46080
#define oAHI 55296
#define oALO 64512
#define ATT_SMEM 73728

__global__ void __launch_bounds__(128, 2) sba_attn()
{
    extern __shared__ char dsm[];
    const uint32_t sb = smem_u32(dsm);

    const int tid = threadIdx.x;
    const int wid = tid >> 5, lane = tid & 31;
    const int warp_m = wid * 16;
    const int ti = (gridDim.x - 1) - blockIdx.x;
    const int bh = blockIdx.y;
    const int i0 = ti * 64;

    const size_t base = (size_t)bh * SEQ * HD;
    const __nv_bfloat16* Qhi_g = g_Qhi + base + (size_t)i0 * HD;
    const __nv_bfloat16* Qlo_g = g_Qlo + base + (size_t)i0 * HD;
    const __nv_bfloat16* Khi_g = g_Khi + base;
    const __nv_bfloat16* Klo_g = g_Klo + base;
    const __nv_bfloat16* Vthi_g = g_Vthi + base;
    const __nv_bfloat16* Vtlo_g = g_Vtlo + base;

#pragma unroll
    for (int t = 0; t < 4; t++) {
        const int flat = t * 128 + tid;
        const int row = flat >> 3, seg = flat & 7;
        const uint32_t off = (uint32_t)(row * 144 + seg * 16);
        CP16(sb + oQHI + off, Qhi_g + row * HD + seg * 8);
        CP16(sb + oQLO + off, Qlo_g + row * HD + seg * 8);
    }
    CP_COMMIT;
    CP_WAIT0;
    __syncthreads();

    const uint32_t a_row = lane & 15;
    const uint32_t a_koff = (lane >> 4) * 8;
    const uint32_t b_row = lane & 7;
    const uint32_t b_koff = ((lane >> 3) & 1) * 8;

    uint32_t qhi[4][4], qlo[4][4];
#pragma unroll
    for (int kk = 0; kk < 4; kk++) {
        const uint32_t off =
            (uint32_t)((warp_m + a_row) * 144 + (kk * 16 + a_koff) * 2);
        ldsm_x4(qhi[kk], sb + oQHI + off);
        ldsm_x4(qlo[kk], sb + oQLO + off);
    }

    float oacc[8][4] = {};
    float accp = 1.0f;
    const int r = lane >> 2;
    const int c2 = (lane & 3) * 2;

    for (int tj = ti; tj >= 0; tj--) {
        const int j0 = tj * 64;
        __syncthreads();

#pragma unroll
        for (int t = 0; t < 4; t++) {
            const int flat = t * 128 + tid;
            const int row = flat >> 3, seg = flat & 7;
            const uint32_t off = (uint32_t)(row * 144 + seg * 16);
            CP16(sb + oKHI + off, Khi_g + (size_t)(j0 + row) * HD + seg * 8);
            CP16(sb + oKLO + off, Klo_g + (size_t)(j0 + row) * HD + seg * 8);
            CP16(sb + oVHI + off, Vthi_g + (size_t)row * SEQ + j0 + seg * 8);
            CP16(sb + oVLO + off, Vtlo_g + (size_t)row * SEQ + j0 + seg * 8);
        }
        CP_COMMIT;
        CP_WAIT0;
        __syncthreads();

        float zacc[8][4] = {};
#pragma unroll
        for (int kk = 0; kk < 4; kk++) {
            uint32_t bh_[8][2], bl_[8][2];
#pragma unroll
            for (int nt = 0; nt < 8; nt++) {
                const uint32_t off =
                    (uint32_t)((nt * 8 + b_row) * 144 + (kk * 16 + b_koff) * 2);
                ldsm_x2(bh_[nt], sb + oKHI + off);
                ldsm_x2(bl_[nt], sb + oKLO + off);
            }
#pragma unroll
            for (int nt = 0; nt < 8; nt++)
                mma16816(zacc[nt], qhi[kk], bh_[nt]);
#pragma unroll
            for (int nt = 0; nt < 8; nt++)
                mma16816(zacc[nt], qhi[kk], bl_[nt]);
#pragma unroll
            for (int nt = 0; nt < 8; nt++)
                mma16816(zacc[nt], qlo[kk], bh_[nt]);
        }

        const bool diag = (tj == ti);
        float* ssp = (float*)(dsm + oSS);
#pragma unroll
        for (int nt = 0; nt < 8; nt++) {
#pragma unroll
            for (int half = 0; half < 2; half++) {
                const int i_loc = warp_m + half * 8 + r;
                float sv0, sv1;
                {
                    const float zv = zacc[nt][half * 2];
                    sv0 = __fdividef(1.0f, 1.0f + __expf(-zv));
                    if (diag && (nt * 8 + c2) >= i_loc) sv0 = 0.0f;
                }
                {
                    const float zv = zacc[nt][half * 2 + 1];
                    sv1 = __fdividef(1.0f, 1.0f + __expf(-zv));
                    if (diag && (nt * 8 + c2 + 1) >= i_loc) sv1 = 0.0f;
                }
                *(float2*)(ssp + i_loc * 66 + nt * 8 + c2) = make_float2(sv0, sv1);
            }
        }
        __syncthreads();

        if (tid < 64) {
            float acc = accp;
            const float* ssr = (float*)(dsm + oSS) + tid * 66;
            __nv_bfloat16* ah = (__nv_bfloat16*)(dsm + oAHI) + tid * ASTR;
            __nv_bfloat16* al = (__nv_bfloat16*)(dsm + oALO) + tid * ASTR;
#pragma unroll
            for (int j = 63; j >= 0; j--) {
                const float sv = ssr[j];
                const float att = sv * acc;
                acc -= att;
                __nv_bfloat16 h, l;
                split2(att, h, l);
                ah[j] = h;
                al[j] = l;
            }
            accp = acc;
        }
        __syncthreads();

#pragma unroll
        for (int kk = 0; kk < 4; kk++) {
            uint32_t ahv[4], alv[4];
            const uint32_t offA =
                (uint32_t)((warp_m + a_row) * 144 + (kk * 16 + a_koff) * 2);
            ldsm_x4(ahv, sb + oAHI + offA);
            ldsm_x4(alv, sb + oALO + offA);
            uint32_t vh[8][2], vl[8][2];
#pragma unroll
            for (int nt = 0; nt < 8; nt++) {
                const uint32_t off =
                    (uint32_t)((nt * 8 + b_row) * 144 + (kk * 16 + b_koff) * 2);
                ldsm_x2(vh[nt], sb + oVHI + off);
                ldsm_x2(vl[nt], sb + oVLO + off);
            }
#pragma unroll
            for (int nt = 0; nt < 8; nt++)
                mma16816(oacc[nt], ahv, vh[nt]);
#pragma unroll
            for (int nt = 0; nt < 8; nt++)
                mma16816(oacc[nt], ahv, vl[nt]);
#pragma unroll
            for (int nt = 0; nt < 8; nt++)
                mma16816(oacc[nt], alv, vh[nt]);
        }
    }

    const int b = bh >> 5, h = bh & 31;
#pragma unroll
    for (int nt = 0; nt < 8; nt++) {
#pragma unroll
        for (int half = 0; half < 2; half++) {
            const int i = i0 + warp_m + half * 8 + r;
            const int d = nt * 8 + c2;
            __nv_bfloat16 h0, l0, h1, l1;
            split2(oacc[nt][half * 2], h0, l0);
            split2(oacc[nt][half * 2 + 1], h1, l1);
            const size_t adr = ((size_t)b * SEQ + i) * HID + h * HD + d;
            *(__nv_bfloat162*)(g_Ohi + adr) = __nv_bfloat162(h0, h1);
            *(__nv_bfloat162*)(g_Olo + adr) = __nv_bfloat162(l0, l1);
        }
    }
}

// ======================= launch =======================
extern "C" void kernel_launch(void* const* d_in, const int* in_sizes, int n_in,
                              void* d_out, int out_size)
{
    const float* X  = (const float*)d_in[0];
    const float* Wq = (const float*)d_in[1];
    const float* Wk = (const float*)d_in[2];
    const float* Wv = (const float*)d_in[3];
    const float* Wo = (const float*)d_in[4];
    float* Out = (float*)d_out;

    cudaFuncSetAttribute(qkv_mma, cudaFuncAttributeMaxDynamicSharedMemorySize,
                         GEMM_SMEM);
    cudaFuncSetAttribute(out_mma, cudaFuncAttributeMaxDynamicSharedMemorySize,
                         GEMM_SMEM);
    cudaFuncSetAttribute(sba_attn, cudaFuncAttributeMaxDynamicSharedMemorySize,
                         ATT_SMEM);

    split5<<<dim3((HID * HID / 4) / 256, 1, 5), 256>>>(X, Wq, Wk, Wv, Wo);
    qkv_mma<<<dim3(HID / 256, (NBATCH * SEQ) / 128, 3), 256, GEMM_SMEM>>>();
    sba_attn<<<dim3(SEQ / 64, NBATCH * NH), 128, ATT_SMEM>>>();
    out_mma<<<dim3(HID / 256, (NBATCH * SEQ) / 128, 1), 256, GEMM_SMEM>>>(Out);
}

// round 7
// speedup vs baseline: 4.5855x; 1.4429x over previous
#include <cuda_runtime.h>
#include <cuda_fp16.h>
#include <cstdint>

#define NBATCH 2
#define SEQ    1024
#define HID    2048
#define NH     32
#define HD     64

// ======================= scratch =======================
#define QKV_ELEMS ((size_t)NBATCH * NH * SEQ * HD)
__device__ __half g_Xhi[(size_t)NBATCH * SEQ * HID];
__device__ __half g_Xlo[(size_t)NBATCH * SEQ * HID];
__device__ __half g_W[4][(size_t)HID * HID];                 // q,k,v,o single fp16
__device__ __half g_Qhi[QKV_ELEMS], g_Qlo[QKV_ELEMS];        // [b,h,l,d], pre-scaled 1/8
__device__ __half g_K[QKV_ELEMS];                            // [b,h,l,d] single
__device__ __half g_Vt[QKV_ELEMS];                           // [b,h,d,l] single, transposed
__device__ __half g_Ohi[(size_t)NBATCH * SEQ * HID];
__device__ __half g_Olo[(size_t)NBATCH * SEQ * HID];

// ======================= helpers =======================
__device__ __forceinline__ uint32_t smem_u32(const void* p) {
    uint32_t a;
    asm("{ .reg .u64 t; cvta.to.shared.u64 t, %1; cvt.u32.u64 %0, t; }"
        : "=r"(a) : "l"(p));
    return a;
}
__device__ __forceinline__ void ldsm_x4(uint32_t* r, uint32_t addr) {
    asm volatile("ldmatrix.sync.aligned.m8n8.x4.shared.b16 {%0,%1,%2,%3}, [%4];"
                 : "=r"(r[0]), "=r"(r[1]), "=r"(r[2]), "=r"(r[3]) : "r"(addr));
}
__device__ __forceinline__ void ldsm_x2(uint32_t* r, uint32_t addr) {
    asm volatile("ldmatrix.sync.aligned.m8n8.x2.shared.b16 {%0,%1}, [%2];"
                 : "=r"(r[0]), "=r"(r[1]) : "r"(addr));
}
__device__ __forceinline__ void mma16816(float* c, const uint32_t* a,
                                         const uint32_t* b) {
    asm("mma.sync.aligned.m16n8k16.row.col.f32.f16.f16.f32 "
        "{%0,%1,%2,%3}, {%4,%5,%6,%7}, {%8,%9}, {%0,%1,%2,%3};"
        : "+f"(c[0]), "+f"(c[1]), "+f"(c[2]), "+f"(c[3])
        : "r"(a[0]), "r"(a[1]), "r"(a[2]), "r"(a[3]), "r"(b[0]), "r"(b[1]));
}
#define CP16(dst, src) \
    asm volatile("cp.async.cg.shared.global [%0], [%1], 16;" \
                 :: "r"(dst), "l"(src) : "memory")
#define CP_COMMIT asm volatile("cp.async.commit_group;" ::: "memory")
#define CP_WAIT0  asm volatile("cp.async.wait_group 0;" ::: "memory")

__device__ __forceinline__ void split2h(float v, __half& h, __half& l) {
    h = __float2half_rn(v);
    l = __float2half_rn(v - __half2float(h));
}

// ======================= fp32 -> fp16 convert / split =======================
__global__ void __launch_bounds__(256)
split5(const float* __restrict__ X, const float* __restrict__ Wq,
       const float* __restrict__ Wk, const float* __restrict__ Wv,
       const float* __restrict__ Wo) {
    const int z = blockIdx.z;
    size_t i4 = ((size_t)blockIdx.x * 256 + threadIdx.x) * 4;
    if (z == 0) {                 // X: split hi/lo
        float4 v = *(const float4*)(X + i4);
        float f[4] = {v.x, v.y, v.z, v.w};
        ushort4 h4, l4;
        unsigned short* hp = &h4.x;
        unsigned short* lp = &l4.x;
#pragma unroll
        for (int k = 0; k < 4; k++) {
            __half bh, bl;
            split2h(f[k], bh, bl);
            hp[k] = __half_as_ushort(bh);
            lp[k] = __half_as_ushort(bl);
        }
        *(ushort4*)(g_Xhi + i4) = h4;
        *(ushort4*)(g_Xlo + i4) = l4;
    } else {                      // weights: single fp16
        const float* src = (z == 1) ? Wq : (z == 2) ? Wk : (z == 3) ? Wv : Wo;
        __half* dst = g_W[z - 1];
        float4 v = *(const float4*)(src + i4);
        ushort4 h4;
        h4.x = __half_as_ushort(__float2half_rn(v.x));
        h4.y = __half_as_ushort(__float2half_rn(v.y));
        h4.z = __half_as_ushort(__float2half_rn(v.z));
        h4.w = __half_as_ushort(__float2half_rn(v.w));
        *(ushort4*)(dst + i4) = h4;
    }
}

// ======================= HMMA fp16 2-term GEMM =======================
// C = (Ahi + Alo) @ B^T, B single fp16. CTA 128x256, BK=64, 8 warps 64x64.
// MODE: 0 = fp32 out; 1 = Q hi/lo scaled 1/8; 2 = K single; 3 = V single transposed.
#define GSTR  72                 // smem row stride (fp16) = 144B
#define oAhi  0
#define oAlo  18432
#define oB    36864
#define STAGE_BYTES 73728
#define GEMM_SMEM (2 * STAGE_BYTES)

template <int MODE>
__device__ __forceinline__ void hmma_gemm_body(
    const __half* __restrict__ Ahi, const __half* __restrict__ Alo,
    const __half* __restrict__ B,
    float* __restrict__ Cf, __half* __restrict__ Chi, __half* __restrict__ Clo)
{
    extern __shared__ char dsm[];
    const uint32_t sb = smem_u32(dsm);

    const int tid = threadIdx.x;
    const int wid = tid >> 5, lane = tid & 31;
    const int warp_m = (wid >> 2) * 64;      // 0 or 64
    const int warp_n = (wid & 3) * 64;       // 0,64,128,192
    const int m0 = blockIdx.y * 128, n0 = blockIdx.x * 256;

    const uint32_t a_row = (lane & 15);
    const uint32_t a_koff = (lane >> 4) * 8;
    const uint32_t b_row = (lane & 7);
    const uint32_t b_koff = ((lane >> 3) & 1) * 8;

    float acc[4][8][4] = {};

    auto load_chunk = [&](int k0, int s) {
        const uint32_t st = sb + s * STAGE_BYTES;
#pragma unroll
        for (int p = 0; p < 4; p++) {        // A: 128 rows x 8 segs (hi+lo)
            const int flat = p * 256 + tid;
            const int row = flat >> 3, seg = flat & 7;
            const uint32_t so = (uint32_t)(row * 144 + seg * 16);
            const size_t ga = (size_t)(m0 + row) * HID + k0 + seg * 8;
            CP16(st + oAhi + so, Ahi + ga);
            CP16(st + oAlo + so, Alo + ga);
        }
#pragma unroll
        for (int p = 0; p < 8; p++) {        // B: 256 rows x 8 segs (single)
            const int flat = p * 256 + tid;
            const int row = flat >> 3, seg = flat & 7;
            const uint32_t so = (uint32_t)(row * 144 + seg * 16);
            const size_t gb = (size_t)(n0 + row) * HID + k0 + seg * 8;
            CP16(st + oB + so, B + gb);
        }
    };

    load_chunk(0, 0);
    CP_COMMIT;

    for (int c = 0; c < HID / 64; c++) {
        CP_WAIT0;
        __syncthreads();
        if (c < HID / 64 - 1) {
            load_chunk((c + 1) * 64, (c + 1) & 1);
            CP_COMMIT;
        }
        const uint32_t st = sb + (c & 1) * STAGE_BYTES;

#pragma unroll
        for (int kk = 0; kk < 64; kk += 16) {
            uint32_t ahi[4][4], alo[4][4];
#pragma unroll
            for (int mi = 0; mi < 4; mi++) {
                const uint32_t off =
                    (uint32_t)((warp_m + mi * 16 + a_row) * GSTR + kk + a_koff) * 2;
                ldsm_x4(ahi[mi], st + oAhi + off);
                ldsm_x4(alo[mi], st + oAlo + off);
            }
#pragma unroll
            for (int nh = 0; nh < 2; nh++) {
                uint32_t bf[4][2];
#pragma unroll
                for (int nj = 0; nj < 4; nj++) {
                    const int ni = nh * 4 + nj;
                    const uint32_t off =
                        (uint32_t)((warp_n + ni * 8 + b_row) * GSTR + kk + b_koff) * 2;
                    ldsm_x2(bf[nj], st + oB + off);
                }
#pragma unroll
                for (int mi = 0; mi < 4; mi++)
#pragma unroll
                    for (int nj = 0; nj < 4; nj++)
                        mma16816(acc[mi][nh * 4 + nj], ahi[mi], bf[nj]);
#pragma unroll
                for (int mi = 0; mi < 4; mi++)
#pragma unroll
                    for (int nj = 0; nj < 4; nj++)
                        mma16816(acc[mi][nh * 4 + nj], alo[mi], bf[nj]);
            }
        }
    }

    // epilogue
    const int tr = lane >> 2;
    const int tc = (lane & 3) * 2;
#pragma unroll
    for (int mi = 0; mi < 4; mi++) {
#pragma unroll
        for (int ni = 0; ni < 8; ni++) {
            const int col = n0 + warp_n + ni * 8 + tc;
#pragma unroll
            for (int half = 0; half < 2; half++) {
                const int row = m0 + warp_m + mi * 16 + half * 8 + tr;
                float v0 = acc[mi][ni][half * 2];
                float v1 = acc[mi][ni][half * 2 + 1];
                if (MODE == 0) {
                    *(float2*)(Cf + (size_t)row * HID + col) = make_float2(v0, v1);
                } else {
                    const int b = row >> 10, l = row & (SEQ - 1);
                    const int h = col >> 6, d = col & 63;
                    if (MODE == 1) {            // Q: scale + hi/lo split
                        v0 *= 0.125f; v1 *= 0.125f;
                        __half h0, l0, h1, l1;
                        split2h(v0, h0, l0);
                        split2h(v1, h1, l1);
                        const size_t adr = (((size_t)b * NH + h) * SEQ + l) * HD + d;
                        *(__half2*)(Chi + adr) = __halves2half2(h0, h1);
                        *(__half2*)(Clo + adr) = __halves2half2(l0, l1);
                    } else if (MODE == 2) {     // K: single
                        const size_t adr = (((size_t)b * NH + h) * SEQ + l) * HD + d;
                        *(__half2*)(Chi + adr) =
                            __halves2half2(__float2half_rn(v0), __float2half_rn(v1));
                    } else {                    // V: single, transposed [d][l]
                        const size_t base = ((size_t)b * NH + h) * HD;
                        Chi[(base + d) * SEQ + l] = __float2half_rn(v0);
                        Chi[(base + d + 1) * SEQ + l] = __float2half_rn(v1);
                    }
                }
            }
        }
    }
}

__global__ void __launch_bounds__(256, 1) qkv_mma() {
    if (blockIdx.z == 0)
        hmma_gemm_body<1>(g_Xhi, g_Xlo, g_W[0], nullptr, g_Qhi, g_Qlo);
    else if (blockIdx.z == 1)
        hmma_gemm_body<2>(g_Xhi, g_Xlo, g_W[1], nullptr, g_K, nullptr);
    else
        hmma_gemm_body<3>(g_Xhi, g_Xlo, g_W[2], nullptr, g_Vt, nullptr);
}

__global__ void __launch_bounds__(256, 1) out_mma(float* Out) {
    hmma_gemm_body<0>(g_Ohi, g_Olo, g_W[3], Out, nullptr, nullptr);
}

// ======================= stick-breaking attention (fp16 2-term HMMA) =======================
#define ASTR 72
#define oSS  0                   // fp32 [64][66], overlays Q (consumed into regs first)
#define oQHI 0
#define oQLO 9216
#define oK   18432
#define oV   27648
#define oAHI 36864
#define oALO 46080
#define ATT_SMEM 55296

__global__ void __launch_bounds__(128, 2) sba_attn()
{
    extern __shared__ char dsm[];
    const uint32_t sb = smem_u32(dsm);

    const int tid = threadIdx.x;
    const int wid = tid >> 5, lane = tid & 31;
    const int warp_m = wid * 16;
    const int ti = (gridDim.x - 1) - blockIdx.x;   // heavy blocks first
    const int bh = blockIdx.y;
    const int i0 = ti * 64;

    const size_t base = (size_t)bh * SEQ * HD;
    const __half* Qhi_g = g_Qhi + base + (size_t)i0 * HD;
    const __half* Qlo_g = g_Qlo + base + (size_t)i0 * HD;
    const __half* K_g   = g_K + base;
    const __half* Vt_g  = g_Vt + base;             // [d][l]

    // ---- load Q tile (64x64 fp16 hi/lo) ----
#pragma unroll
    for (int t = 0; t < 4; t++) {
        const int flat = t * 128 + tid;
        const int row = flat >> 3, seg = flat & 7;
        const uint32_t off = (uint32_t)(row * 144 + seg * 16);
        CP16(sb + oQHI + off, Qhi_g + row * HD + seg * 8);
        CP16(sb + oQLO + off, Qlo_g + row * HD + seg * 8);
    }
    CP_COMMIT;
    CP_WAIT0;
    __syncthreads();

    const uint32_t a_row = lane & 15;
    const uint32_t a_koff = (lane >> 4) * 8;
    const uint32_t b_row = lane & 7;
    const uint32_t b_koff = ((lane >> 3) & 1) * 8;

    uint32_t qhi[4][4], qlo[4][4];
#pragma unroll
    for (int kk = 0; kk < 4; kk++) {
        const uint32_t off =
            (uint32_t)((warp_m + a_row) * 144 + (kk * 16 + a_koff) * 2);
        ldsm_x4(qhi[kk], sb + oQHI + off);
        ldsm_x4(qlo[kk], sb + oQLO + off);
    }

    float oacc[8][4] = {};
    float accp = 1.0f;
    const int r = lane >> 2;
    const int c2 = (lane & 3) * 2;

    for (int tj = ti; tj >= 0; tj--) {
        const int j0 = tj * 64;
        __syncthreads();

        // ---- load K [j][d] and Vt [d][j0+j] tiles (single fp16) ----
#pragma unroll
        for (int t = 0; t < 4; t++) {
            const int flat = t * 128 + tid;
            const int row = flat >> 3, seg = flat & 7;
            const uint32_t off = (uint32_t)(row * 144 + seg * 16);
            CP16(sb + oK + off, K_g + (size_t)(j0 + row) * HD + seg * 8);
            CP16(sb + oV + off, Vt_g + (size_t)row * SEQ + j0 + seg * 8);
        }
        CP_COMMIT;
        CP_WAIT0;
        __syncthreads();

        // ---- z = (Qhi+Qlo)/8 · K^T ----
        float zacc[8][4] = {};
#pragma unroll
        for (int kk = 0; kk < 4; kk++) {
            uint32_t bh_[8][2];
#pragma unroll
            for (int nt = 0; nt < 8; nt++) {
                const uint32_t off =
                    (uint32_t)((nt * 8 + b_row) * 144 + (kk * 16 + b_koff) * 2);
                ldsm_x2(bh_[nt], sb + oK + off);
            }
#pragma unroll
            for (int nt = 0; nt < 8; nt++)
                mma16816(zacc[nt], qhi[kk], bh_[nt]);
#pragma unroll
            for (int nt = 0; nt < 8; nt++)
                mma16816(zacc[nt], qlo[kk], bh_[nt]);
        }

        // ---- sigmoid + causal mask -> Ss[i][j] (fp32) ----
        const bool diag = (tj == ti);
        float* ssp = (float*)(dsm + oSS);
#pragma unroll
        for (int nt = 0; nt < 8; nt++) {
#pragma unroll
            for (int half = 0; half < 2; half++) {
                const int i_loc = warp_m + half * 8 + r;
                float sv0, sv1;
                {
                    const float zv = zacc[nt][half * 2];
                    sv0 = __fdividef(1.0f, 1.0f + __expf(-zv));
                    if (diag && (nt * 8 + c2) >= i_loc) sv0 = 0.0f;
                }
                {
                    const float zv = zacc[nt][half * 2 + 1];
                    sv1 = __fdividef(1.0f, 1.0f + __expf(-zv));
                    if (diag && (nt * 8 + c2 + 1) >= i_loc) sv1 = 0.0f;
                }
                *(float2*)(ssp + i_loc * 66 + nt * 8 + c2) = make_float2(sv0, sv1);
            }
        }
        __syncthreads();

        // ---- per-row suffix-product scan, emit att as fp16 hi/lo ----
        if (tid < 64) {
            float acc = accp;
            const float* ssr = (float*)(dsm + oSS) + tid * 66;
            __half* ah = (__half*)(dsm + oAHI) + tid * ASTR;
            __half* al = (__half*)(dsm + oALO) + tid * ASTR;
#pragma unroll
            for (int j = 63; j >= 0; j--) {
                const float sv = ssr[j];
                const float att = sv * acc;
                acc -= att;                       // acc *= (1 - sv)
                __half h, l;
                split2h(att, h, l);
                ah[j] = h;
                al[j] = l;
            }
            accp = acc;
        }
        __syncthreads();

        // ---- O += (att_hi + att_lo) @ V ----
#pragma unroll
        for (int kk = 0; kk < 4; kk++) {
            uint32_t ahv[4], alv[4];
            const uint32_t offA =
                (uint32_t)((warp_m + a_row) * 144 + (kk * 16 + a_koff) * 2);
            ldsm_x4(ahv, sb + oAHI + offA);
            ldsm_x4(alv, sb + oALO + offA);
            uint32_t vh[8][2];
#pragma unroll
            for (int nt = 0; nt < 8; nt++) {
                const uint32_t off =
                    (uint32_t)((nt * 8 + b_row) * 144 + (kk * 16 + b_koff) * 2);
                ldsm_x2(vh[nt], sb + oV + off);
            }
#pragma unroll
            for (int nt = 0; nt < 8; nt++)
                mma16816(oacc[nt], ahv, vh[nt]);
#pragma unroll
            for (int nt = 0; nt < 8; nt++)
                mma16816(oacc[nt], alv, vh[nt]);
        }
    }

    // ---- epilogue: write O as fp16 hi/lo, flat [b, l, h*64+d] ----
    const int b = bh >> 5, h = bh & 31;
#pragma unroll
    for (int nt = 0; nt < 8; nt++) {
#pragma unroll
        for (int half = 0; half < 2; half++) {
            const int i = i0 + warp_m + half * 8 + r;
            const int d = nt * 8 + c2;
            __half h0, l0, h1, l1;
            split2h(oacc[nt][half * 2], h0, l0);
            split2h(oacc[nt][half * 2 + 1], h1, l1);
            const size_t adr = ((size_t)b * SEQ + i) * HID + h * HD + d;
            *(__half2*)(g_Ohi + adr) = __halves2half2(h0, h1);
            *(__half2*)(g_Olo + adr) = __halves2half2(l0, l1);
        }
    }
}

// ======================= launch =======================
extern "C" void kernel_launch(void* const* d_in, const int* in_sizes, int n_in,
                              void* d_out, int out_size)
{
    const float* X  = (const float*)d_in[0];
    const float* Wq = (const float*)d_in[1];
    const float* Wk = (const float*)d_in[2];
    const float* Wv = (const float*)d_in[3];
    const float* Wo = (const float*)d_in[4];
    float* Out = (float*)d_out;

    cudaFuncSetAttribute(qkv_mma, cudaFuncAttributeMaxDynamicSharedMemorySize,
                         GEMM_SMEM);
    cudaFuncSetAttribute(out_mma, cudaFuncAttributeMaxDynamicSharedMemorySize,
                         GEMM_SMEM);
    cudaFuncSetAttribute(sba_attn, cudaFuncAttributeMaxDynamicSharedMemorySize,
                         ATT_SMEM);

    split5<<<dim3((HID * HID / 4) / 256, 1, 5), 256>>>(X, Wq, Wk, Wv, Wo);
    qkv_mma<<<dim3(HID / 256, (NBATCH * SEQ) / 128, 3), 256, GEMM_SMEM>>>();
    sba_attn<<<dim3(SEQ / 64, NBATCH * NH), 128, ATT_SMEM>>>();
    out_mma<<<dim3(HID / 256, (NBATCH * SEQ) / 128, 1), 256, GEMM_SMEM>>>(Out);
}

// round 8
// speedup vs baseline: 7.1654x; 1.5626x over previous
#include <cuda_runtime.h>
#include <cuda_fp16.h>
#include <cstdint>

#define NBATCH 2
#define SEQ    1024
#define HID    2048
#define NH     32
#define HD     64

// ======================= scratch =======================
#define QKV_ELEMS ((size_t)NBATCH * NH * SEQ * HD)
__device__ __half g_X[(size_t)NBATCH * SEQ * HID];
__device__ __half g_W[4][(size_t)HID * HID];     // q,k,v,o
__device__ __half g_Q[QKV_ELEMS];                // [b,h,l,d], pre-scaled 1/8
__device__ __half g_K[QKV_ELEMS];                // [b,h,l,d]
__device__ __half g_Vt[QKV_ELEMS];               // [b,h,d,l] transposed
__device__ __half g_O[(size_t)NBATCH * SEQ * HID];

// ======================= helpers =======================
__device__ __forceinline__ uint32_t smem_u32(const void* p) {
    uint32_t a;
    asm("{ .reg .u64 t; cvta.to.shared.u64 t, %1; cvt.u32.u64 %0, t; }"
        : "=r"(a) : "l"(p));
    return a;
}
__device__ __forceinline__ void ldsm_x4(uint32_t* r, uint32_t addr) {
    asm volatile("ldmatrix.sync.aligned.m8n8.x4.shared.b16 {%0,%1,%2,%3}, [%4];"
                 : "=r"(r[0]), "=r"(r[1]), "=r"(r[2]), "=r"(r[3]) : "r"(addr));
}
__device__ __forceinline__ void ldsm_x2(uint32_t* r, uint32_t addr) {
    asm volatile("ldmatrix.sync.aligned.m8n8.x2.shared.b16 {%0,%1}, [%2];"
                 : "=r"(r[0]), "=r"(r[1]) : "r"(addr));
}
__device__ __forceinline__ void mma16816(float* c, const uint32_t* a,
                                         const uint32_t* b) {
    asm("mma.sync.aligned.m16n8k16.row.col.f32.f16.f16.f32 "
        "{%0,%1,%2,%3}, {%4,%5,%6,%7}, {%8,%9}, {%0,%1,%2,%3};"
        : "+f"(c[0]), "+f"(c[1]), "+f"(c[2]), "+f"(c[3])
        : "r"(a[0]), "r"(a[1]), "r"(a[2]), "r"(a[3]), "r"(b[0]), "r"(b[1]));
}
#define CP16(dst, src) \
    asm volatile("cp.async.cg.shared.global [%0], [%1], 16;" \
                 :: "r"(dst), "l"(src) : "memory")
#define CP_COMMIT asm volatile("cp.async.commit_group;" ::: "memory")
#define CP_WAIT0  asm volatile("cp.async.wait_group 0;" ::: "memory")

// ======================= fp32 -> fp16 convert =======================
__global__ void __launch_bounds__(256)
cvt5(const float* __restrict__ X, const float* __restrict__ Wq,
     const float* __restrict__ Wk, const float* __restrict__ Wv,
     const float* __restrict__ Wo) {
    const int z = blockIdx.z;
    const float* src = (z == 0) ? X : (z == 1) ? Wq : (z == 2) ? Wk
                                   : (z == 3) ? Wv : Wo;
    __half* dst = (z == 0) ? g_X : g_W[z - 1];
    size_t i4 = ((size_t)blockIdx.x * 256 + threadIdx.x) * 4;
    float4 v = *(const float4*)(src + i4);
    ushort4 h4;
    h4.x = __half_as_ushort(__float2half_rn(v.x));
    h4.y = __half_as_ushort(__float2half_rn(v.y));
    h4.z = __half_as_ushort(__float2half_rn(v.z));
    h4.w = __half_as_ushort(__float2half_rn(v.w));
    *(ushort4*)(dst + i4) = h4;
}

// ======================= HMMA fp16 GEMM =======================
// C = A @ B^T, single fp16 both sides. CTA 128x256, BK=128, 8 warps 64x64.
// MODE: 0 = fp32 out; 1 = Q scaled 1/8; 2 = K; 3 = V transposed.
#define GSTR  136                // fp16 elems per smem row = 272B
#define oA    0
#define oB    34816
#define STAGE_BYTES 104448       // A 128*272 + B 256*272
#define GEMM_SMEM (2 * STAGE_BYTES)

template <int MODE>
__device__ __forceinline__ void hmma_gemm_body(
    const __half* __restrict__ A, const __half* __restrict__ B,
    float* __restrict__ Cf, __half* __restrict__ Ch)
{
    extern __shared__ char dsm[];
    const uint32_t sb = smem_u32(dsm);

    const int tid = threadIdx.x;
    const int wid = tid >> 5, lane = tid & 31;
    const int warp_m = (wid >> 2) * 64;      // 0 or 64
    const int warp_n = (wid & 3) * 64;       // 0,64,128,192
    const int m0 = blockIdx.y * 128, n0 = blockIdx.x * 256;

    const uint32_t a_row = (lane & 15);
    const uint32_t a_koff = (lane >> 4) * 8;
    const uint32_t b_row = (lane & 7);
    const uint32_t b_koff = ((lane >> 3) & 1) * 8;

    float acc[4][8][4] = {};

    auto load_chunk = [&](int k0, int s) {
        const uint32_t st = sb + s * STAGE_BYTES;
#pragma unroll
        for (int p = 0; p < 8; p++) {        // A: 128 rows x 16 segs
            const int flat = p * 256 + tid;
            const int row = flat >> 4, seg = flat & 15;
            const uint32_t so = (uint32_t)(row * 272 + seg * 16);
            CP16(st + oA + so, A + (size_t)(m0 + row) * HID + k0 + seg * 8);
        }
#pragma unroll
        for (int p = 0; p < 16; p++) {       // B: 256 rows x 16 segs
            const int flat = p * 256 + tid;
            const int row = flat >> 4, seg = flat & 15;
            const uint32_t so = (uint32_t)(row * 272 + seg * 16);
            CP16(st + oB + so, B + (size_t)(n0 + row) * HID + k0 + seg * 8);
        }
    };

    load_chunk(0, 0);
    CP_COMMIT;

    for (int c = 0; c < HID / 128; c++) {
        CP_WAIT0;
        __syncthreads();
        if (c < HID / 128 - 1) {
            load_chunk((c + 1) * 128, (c + 1) & 1);
            CP_COMMIT;
        }
        const uint32_t st = sb + (c & 1) * STAGE_BYTES;

#pragma unroll
        for (int kk = 0; kk < 128; kk += 16) {
            uint32_t af[4][4];
#pragma unroll
            for (int mi = 0; mi < 4; mi++) {
                const uint32_t off =
                    (uint32_t)((warp_m + mi * 16 + a_row) * GSTR + kk + a_koff) * 2;
                ldsm_x4(af[mi], st + oA + off);
            }
#pragma unroll
            for (int nh = 0; nh < 2; nh++) {
                uint32_t bf[4][2];
#pragma unroll
                for (int nj = 0; nj < 4; nj++) {
                    const int ni = nh * 4 + nj;
                    const uint32_t off =
                        (uint32_t)((warp_n + ni * 8 + b_row) * GSTR + kk + b_koff) * 2;
                    ldsm_x2(bf[nj], st + oB + off);
                }
#pragma unroll
                for (int mi = 0; mi < 4; mi++)
#pragma unroll
                    for (int nj = 0; nj < 4; nj++)
                        mma16816(acc[mi][nh * 4 + nj], af[mi], bf[nj]);
            }
        }
    }

    // epilogue
    const int tr = lane >> 2;
    const int tc = (lane & 3) * 2;
#pragma unroll
    for (int mi = 0; mi < 4; mi++) {
#pragma unroll
        for (int ni = 0; ni < 8; ni++) {
            const int col = n0 + warp_n + ni * 8 + tc;
#pragma unroll
            for (int half = 0; half < 2; half++) {
                const int row = m0 + warp_m + mi * 16 + half * 8 + tr;
                float v0 = acc[mi][ni][half * 2];
                float v1 = acc[mi][ni][half * 2 + 1];
                if (MODE == 0) {
                    *(float2*)(Cf + (size_t)row * HID + col) = make_float2(v0, v1);
                } else {
                    const int b = row >> 10, l = row & (SEQ - 1);
                    const int h = col >> 6, d = col & 63;
                    if (MODE == 1) { v0 *= 0.125f; v1 *= 0.125f; }
                    if (MODE == 3) {             // V: transposed [d][l]
                        const size_t base = ((size_t)b * NH + h) * HD;
                        Ch[(base + d) * SEQ + l] = __float2half_rn(v0);
                        Ch[(base + d + 1) * SEQ + l] = __float2half_rn(v1);
                    } else {
                        const size_t adr = (((size_t)b * NH + h) * SEQ + l) * HD + d;
                        *(__half2*)(Ch + adr) =
                            __halves2half2(__float2half_rn(v0), __float2half_rn(v1));
                    }
                }
            }
        }
    }
}

__global__ void __launch_bounds__(256, 1) qkv_mma() {
    if (blockIdx.z == 0)
        hmma_gemm_body<1>(g_X, g_W[0], nullptr, g_Q);
    else if (blockIdx.z == 1)
        hmma_gemm_body<2>(g_X, g_W[1], nullptr, g_K);
    else
        hmma_gemm_body<3>(g_X, g_W[2], nullptr, g_Vt);
}

__global__ void __launch_bounds__(256, 1) out_mma(float* Out) {
    hmma_gemm_body<0>(g_O, g_W[3], Out, nullptr);
}

// ======================= stick-breaking attention (fp16 HMMA) =======================
#define ASTR 72
#define oQ   0
#define oK_  9216
#define oV_  18432
#define oAT  27648
#define oSS  36864               // fp32 [64][66]
#define ATT_SMEM (36864 + 64 * 66 * 4)

__global__ void __launch_bounds__(128, 2) sba_attn()
{
    extern __shared__ char dsm[];
    const uint32_t sb = smem_u32(dsm);

    const int tid = threadIdx.x;
    const int wid = tid >> 5, lane = tid & 31;
    const int warp_m = wid * 16;
    const int ti = (gridDim.x - 1) - blockIdx.x;   // heavy blocks first
    const int bh = blockIdx.y;
    const int i0 = ti * 64;

    const size_t base = (size_t)bh * SEQ * HD;
    const __half* Q_g  = g_Q + base + (size_t)i0 * HD;
    const __half* K_g  = g_K + base;
    const __half* Vt_g = g_Vt + base;              // [d][l]

    // ---- load Q tile (64x64 fp16) ----
#pragma unroll
    for (int t = 0; t < 4; t++) {
        const int flat = t * 128 + tid;
        const int row = flat >> 3, seg = flat & 7;
        const uint32_t off = (uint32_t)(row * 144 + seg * 16);
        CP16(sb + oQ + off, Q_g + row * HD + seg * 8);
    }
    CP_COMMIT;
    CP_WAIT0;
    __syncthreads();

    const uint32_t a_row = lane & 15;
    const uint32_t a_koff = (lane >> 4) * 8;
    const uint32_t b_row = lane & 7;
    const uint32_t b_koff = ((lane >> 3) & 1) * 8;

    uint32_t qf[4][4];
#pragma unroll
    for (int kk = 0; kk < 4; kk++) {
        const uint32_t off =
            (uint32_t)((warp_m + a_row) * 144 + (kk * 16 + a_koff) * 2);
        ldsm_x4(qf[kk], sb + oQ + off);
    }

    float oacc[8][4] = {};
    float accp = 1.0f;
    const int r = lane >> 2;
    const int c2 = (lane & 3) * 2;

    for (int tj = ti; tj >= 0; tj--) {
        const int j0 = tj * 64;
        __syncthreads();

        // ---- load K [j][d] and Vt [d][j0+j] tiles ----
#pragma unroll
        for (int t = 0; t < 4; t++) {
            const int flat = t * 128 + tid;
            const int row = flat >> 3, seg = flat & 7;
            const uint32_t off = (uint32_t)(row * 144 + seg * 16);
            CP16(sb + oK_ + off, K_g + (size_t)(j0 + row) * HD + seg * 8);
            CP16(sb + oV_ + off, Vt_g + (size_t)row * SEQ + j0 + seg * 8);
        }
        CP_COMMIT;
        CP_WAIT0;
        __syncthreads();

        // ---- z = Q K^T (Q pre-scaled) ----
        float zacc[8][4] = {};
#pragma unroll
        for (int kk = 0; kk < 4; kk++) {
            uint32_t kf[8][2];
#pragma unroll
            for (int nt = 0; nt < 8; nt++) {
                const uint32_t off =
                    (uint32_t)((nt * 8 + b_row) * 144 + (kk * 16 + b_koff) * 2);
                ldsm_x2(kf[nt], sb + oK_ + off);
            }
#pragma unroll
            for (int nt = 0; nt < 8; nt++)
                mma16816(zacc[nt], qf[kk], kf[nt]);
        }

        // ---- sigmoid + causal mask -> Ss[i][j] (fp32) ----
        const bool diag = (tj == ti);
        float* ssp = (float*)(dsm + oSS);
#pragma unroll
        for (int nt = 0; nt < 8; nt++) {
#pragma unroll
            for (int half = 0; half < 2; half++) {
                const int i_loc = warp_m + half * 8 + r;
                float sv0, sv1;
                {
                    const float zv = zacc[nt][half * 2];
                    sv0 = __fdividef(1.0f, 1.0f + __expf(-zv));
                    if (diag && (nt * 8 + c2) >= i_loc) sv0 = 0.0f;
                }
                {
                    const float zv = zacc[nt][half * 2 + 1];
                    sv1 = __fdividef(1.0f, 1.0f + __expf(-zv));
                    if (diag && (nt * 8 + c2 + 1) >= i_loc) sv1 = 0.0f;
                }
                *(float2*)(ssp + i_loc * 66 + nt * 8 + c2) = make_float2(sv0, sv1);
            }
        }
        __syncthreads();

        // ---- per-row suffix-product scan, emit att as fp16 ----
        if (tid < 64) {
            float acc = accp;
            const float* ssr = (float*)(dsm + oSS) + tid * 66;
            __half* ah = (__half*)(dsm + oAT) + tid * ASTR;
#pragma unroll
            for (int j = 63; j >= 0; j--) {
                const float sv = ssr[j];
                const float att = sv * acc;
                acc -= att;                       // acc *= (1 - sv)
                ah[j] = __float2half_rn(att);
            }
            accp = acc;
        }
        __syncthreads();

        // ---- O += att @ V ----
#pragma unroll
        for (int kk = 0; kk < 4; kk++) {
            uint32_t av[4];
            const uint32_t offA =
                (uint32_t)((warp_m + a_row) * 144 + (kk * 16 + a_koff) * 2);
            ldsm_x4(av, sb + oAT + offA);
            uint32_t vf[8][2];
#pragma unroll
            for (int nt = 0; nt < 8; nt++) {
                const uint32_t off =
                    (uint32_t)((nt * 8 + b_row) * 144 + (kk * 16 + b_koff) * 2);
                ldsm_x2(vf[nt], sb + oV_ + off);
            }
#pragma unroll
            for (int nt = 0; nt < 8; nt++)
                mma16816(oacc[nt], av, vf[nt]);
        }
    }

    // ---- epilogue: write O fp16, flat [b, l, h*64+d] ----
    const int b = bh >> 5, h = bh & 31;
#pragma unroll
    for (int nt = 0; nt < 8; nt++) {
#pragma unroll
        for (int half = 0; half < 2; half++) {
            const int i = i0 + warp_m + half * 8 + r;
            const int d = nt * 8 + c2;
            const size_t adr = ((size_t)b * SEQ + i) * HID + h * HD + d;
            *(__half2*)(g_O + adr) =
                __halves2half2(__float2half_rn(oacc[nt][half * 2]),
                               __float2half_rn(oacc[nt][half * 2 + 1]));
        }
    }
}

// ======================= launch =======================
extern "C" void kernel_launch(void* const* d_in, const int* in_sizes, int n_in,
                              void* d_out, int out_size)
{
    const float* X  = (const float*)d_in[0];
    const float* Wq = (const float*)d_in[1];
    const float* Wk = (const float*)d_in[2];
    const float* Wv = (const float*)d_in[3];
    const float* Wo = (const float*)d_in[4];
    float* Out = (float*)d_out;

    cudaFuncSetAttribute(qkv_mma, cudaFuncAttributeMaxDynamicSharedMemorySize,
                         GEMM_SMEM);
    cudaFuncSetAttribute(out_mma, cudaFuncAttributeMaxDynamicSharedMemorySize,
                         GEMM_SMEM);
    cudaFuncSetAttribute(sba_attn, cudaFuncAttributeMaxDynamicSharedMemorySize,
                         ATT_SMEM);

    cvt5<<<dim3((HID * HID / 4) / 256, 1, 5), 256>>>(X, Wq, Wk, Wv, Wo);
    qkv_mma<<<dim3(HID / 256, (NBATCH * SEQ) / 128, 3), 256, GEMM_SMEM>>>();
    sba_attn<<<dim3(SEQ / 64, NBATCH * NH), 128, ATT_SMEM>>>();
    out_mma<<<dim3(HID / 256, (NBATCH * SEQ) / 128, 1), 256, GEMM_SMEM>>>(Out);
}